// round 1
// baseline (speedup 1.0000x reference)
#include <cuda_runtime.h>
#include <math.h>

// ---------------- problem constants ----------------
#define TOK   65536          // 2*32*32*32 tokens
#define CDIM  512
#define QKVN  1536
#define HIDN  2048
#define NWIN  1024           // windows total (2 * 8^3)
#define NHEAD 8
#define HD    64

// ---------------- scratch (static device memory; no allocs in launch) ----
__device__ float g_y1  [(size_t)TOK * CDIM];   // LN1 output, window-ordered
__device__ float g_qkv [(size_t)TOK * QKVN];   // qkv, window-ordered
__device__ float g_attn[(size_t)TOK * CDIM];   // attention out, window-ordered
__device__ float g_xo  [(size_t)TOK * CDIM];   // post-attn residual, natural order
__device__ float g_y2  [(size_t)TOK * CDIM];   // LN2 output, natural order
__device__ float g_hid [(size_t)TOK * HIDN];   // FFN hidden (post-GELU), natural

// window-ordered row r -> natural token index t
// r = (((b*8+wd)*8+wh)*8+ww)*64 + ((zd*4+zh)*4+zw)
// shifted coord = w*4+z ; natural = shifted + 2 (mod 32)  [roll(-2) inverse]
__device__ __forceinline__ int wr2t(int r) {
    int n   = r & 63;
    int win = r >> 6;
    int ww  = win & 7, wh = (win >> 3) & 7, wd = (win >> 6) & 7, b = win >> 9;
    int zw  = n & 3,  zh = (n >> 2) & 3,  zd = n >> 4;
    int d = (wd * 4 + zd + 2) & 31;
    int h = (wh * 4 + zh + 2) & 31;
    int w = (ww * 4 + zw + 2) & 31;
    return ((b * 32 + d) * 32 + h) * 32 + w;
}

__device__ __forceinline__ float gelu_exact(float v) {
    return 0.5f * v * (1.0f + erff(v * 0.70710678118654752f));
}

// ---------------- LayerNorm (one block per row, 256 threads) -------------
__global__ __launch_bounds__(256)
void ln_kernel(const float* __restrict__ X, const float* __restrict__ gam,
               const float* __restrict__ bet, float* __restrict__ Y, int gather)
{
    __shared__ float red[16];
    int r   = blockIdx.x;
    int src = gather ? wr2t(r) : r;
    const float* xr = X + (size_t)src * CDIM;
    int t = threadIdx.x;
    float v0 = xr[t], v1 = xr[t + 256];
    float s = v0 + v1;
    float q = v0 * v0 + v1 * v1;
    #pragma unroll
    for (int off = 16; off > 0; off >>= 1) {
        s += __shfl_xor_sync(0xffffffffu, s, off);
        q += __shfl_xor_sync(0xffffffffu, q, off);
    }
    int w = t >> 5, lane = t & 31;
    if (lane == 0) { red[w] = s; red[8 + w] = q; }
    __syncthreads();
    if (w == 0) {
        float s2 = (lane < 8) ? red[lane] : 0.f;
        float q2 = (lane < 8) ? red[8 + lane] : 0.f;
        #pragma unroll
        for (int off = 4; off > 0; off >>= 1) {
            s2 += __shfl_xor_sync(0xffffffffu, s2, off);
            q2 += __shfl_xor_sync(0xffffffffu, q2, off);
        }
        if (lane == 0) { red[0] = s2; red[1] = q2; }
    }
    __syncthreads();
    float mean = red[0] * (1.0f / CDIM);
    float var  = red[1] * (1.0f / CDIM) - mean * mean;
    float rstd = rsqrtf(var + 1e-5f);
    float* yr = Y + (size_t)r * CDIM;
    yr[t]       = (v0 - mean) * rstd * gam[t]       + bet[t];
    yr[t + 256] = (v1 - mean) * rstd * gam[t + 256] + bet[t + 256];
}

// ---------------- SGEMM: C[M,N] = A[M,K] @ B[K,N] + bias, fused epilogues -
// 128x128 block tile, BK=16, 256 threads, 8x8 per-thread tile, smem double buffer
#define BM 128
#define BN 128
#define BK 16

#define EPI_NONE    0
#define EPI_GELU    1
#define EPI_RES_MAP 2   // out row & residual row = wr2t(r); R = residual src
#define EPI_RES_NAT 3   // out row = r;            R = residual src

template<int EPI>
__global__ __launch_bounds__(256, 2)
void gemm_kernel(const float* __restrict__ A, const float* __restrict__ B,
                 const float* __restrict__ bias, const float* __restrict__ R,
                 float* __restrict__ C, int M, int N, int K)
{
    __shared__ float As[2][BK][BM];   // transposed: [k][m]
    __shared__ float Bs[2][BK][BN];   // natural:    [k][n]

    const int tid  = threadIdx.x;
    const int tx   = tid & 15;
    const int ty   = tid >> 4;
    const int row0 = blockIdx.y * BM;
    const int col0 = blockIdx.x * BN;

    float acc[8][8] = {};
    float4 ra[2], rb[2];

    // prefetch k-tile 0
    #pragma unroll
    for (int i = 0; i < 2; i++) {
        int f = tid + i * 256;
        int arow = f >> 2, ak = (f & 3) * 4;
        ra[i] = *(const float4*)(A + (size_t)(row0 + arow) * K + ak);
        int bk = f >> 5, bn = (f & 31) * 4;
        rb[i] = *(const float4*)(B + (size_t)bk * N + col0 + bn);
    }
    int buf = 0;
    #pragma unroll
    for (int i = 0; i < 2; i++) {
        int f = tid + i * 256;
        int arow = f >> 2, ak = (f & 3) * 4;
        As[buf][ak + 0][arow] = ra[i].x;
        As[buf][ak + 1][arow] = ra[i].y;
        As[buf][ak + 2][arow] = ra[i].z;
        As[buf][ak + 3][arow] = ra[i].w;
        int bk = f >> 5, bn = (f & 31) * 4;
        *(float4*)&Bs[buf][bk][bn] = rb[i];
    }
    __syncthreads();

    for (int kt = 0; kt < K; kt += BK) {
        int nxt = kt + BK;
        if (nxt < K) {
            #pragma unroll
            for (int i = 0; i < 2; i++) {
                int f = tid + i * 256;
                int arow = f >> 2, ak = (f & 3) * 4;
                ra[i] = *(const float4*)(A + (size_t)(row0 + arow) * K + nxt + ak);
                int bk = f >> 5, bn = (f & 31) * 4;
                rb[i] = *(const float4*)(B + (size_t)(nxt + bk) * N + col0 + bn);
            }
        }
        #pragma unroll
        for (int kk = 0; kk < BK; kk++) {
            float4 a0 = *(const float4*)&As[buf][kk][ty * 4];
            float4 a1 = *(const float4*)&As[buf][kk][64 + ty * 4];
            float4 b0 = *(const float4*)&Bs[buf][kk][tx * 4];
            float4 b1 = *(const float4*)&Bs[buf][kk][64 + tx * 4];
            float av[8] = {a0.x, a0.y, a0.z, a0.w, a1.x, a1.y, a1.z, a1.w};
            float bv[8] = {b0.x, b0.y, b0.z, b0.w, b1.x, b1.y, b1.z, b1.w};
            #pragma unroll
            for (int i = 0; i < 8; i++)
                #pragma unroll
                for (int j = 0; j < 8; j++)
                    acc[i][j] = fmaf(av[i], bv[j], acc[i][j]);
        }
        if (nxt < K) {
            buf ^= 1;
            #pragma unroll
            for (int i = 0; i < 2; i++) {
                int f = tid + i * 256;
                int arow = f >> 2, ak = (f & 3) * 4;
                As[buf][ak + 0][arow] = ra[i].x;
                As[buf][ak + 1][arow] = ra[i].y;
                As[buf][ak + 2][arow] = ra[i].z;
                As[buf][ak + 3][arow] = ra[i].w;
                int bk = f >> 5, bn = (f & 31) * 4;
                *(float4*)&Bs[buf][bk][bn] = rb[i];
            }
            __syncthreads();
        }
    }

    // epilogue
    #pragma unroll
    for (int mi = 0; mi < 8; mi++) {
        int lrow = (mi < 4) ? (ty * 4 + mi) : (64 + ty * 4 + mi - 4);
        int grow = row0 + lrow;
        int orow = (EPI == EPI_RES_MAP) ? wr2t(grow) : grow;
        #pragma unroll
        for (int hh = 0; hh < 2; hh++) {
            int lcol = (hh ? 64 : 0) + tx * 4;
            int gcol = col0 + lcol;
            float4 ov;
            float* o = (float*)&ov;
            #pragma unroll
            for (int j = 0; j < 4; j++) {
                float v = acc[mi][hh * 4 + j] + bias[gcol + j];
                if (EPI == EPI_GELU) v = gelu_exact(v);
                if (EPI == EPI_RES_MAP || EPI == EPI_RES_NAT)
                    v += R[(size_t)orow * N + gcol + j];
                o[j] = v;
            }
            *(float4*)(C + (size_t)orow * N + gcol) = ov;
        }
    }
}

// ---------------- windowed attention: one block per (window, head) -------
// smem: qts[64][65] (d-major), kts[64][65] (d-major), vs[64][64]; ps reuses qts
__global__ __launch_bounds__(256)
void attn_kernel(const float* __restrict__ qkv, float* __restrict__ out)
{
    extern __shared__ float sm[];
    float* qts = sm;                  // 64*65
    float* kts = sm + 64 * 65;        // 64*65
    float* vs  = sm + 2 * 64 * 65;    // 64*64
    float* ps  = sm;                  // reuse qts region for probs

    const int tid  = threadIdx.x;
    const int win  = blockIdx.x >> 3;
    const int head = blockIdx.x & 7;
    const size_t base0 = (size_t)win * 64 * QKVN + head * HD;

    for (int e = tid; e < 4096; e += 256) {
        int n = e >> 6, dd = e & 63;
        size_t base = base0 + (size_t)n * QKVN + dd;
        qts[dd * 65 + n] = qkv[base];
        kts[dd * 65 + n] = qkv[base + 512];
        vs[n * 64 + dd]  = qkv[base + 1024];
    }
    __syncthreads();

    const int tx = tid & 15, ty = tid >> 4;

    // logits (4x4 per thread)
    float acc[4][4] = {};
    #pragma unroll 4
    for (int dd = 0; dd < 64; dd++) {
        float qa[4], kb[4];
        #pragma unroll
        for (int i = 0; i < 4; i++) qa[i] = qts[dd * 65 + ty * 4 + i];
        #pragma unroll
        for (int j = 0; j < 4; j++) kb[j] = kts[dd * 65 + tx * 4 + j];
        #pragma unroll
        for (int i = 0; i < 4; i++)
            #pragma unroll
            for (int j = 0; j < 4; j++)
                acc[i][j] = fmaf(qa[i], kb[j], acc[i][j]);
    }
    __syncthreads();   // everyone done reading qts before overwrite as ps
    #pragma unroll
    for (int i = 0; i < 4; i++)
        #pragma unroll
        for (int j = 0; j < 4; j++)
            ps[(ty * 4 + i) * 64 + tx * 4 + j] = acc[i][j] * 0.125f;  // HD^-0.5
    __syncthreads();

    // softmax, 8 rows per warp
    {
        int w = tid >> 5, lane = tid & 31;
        #pragma unroll
        for (int rr = 0; rr < 8; rr++) {
            int row = w * 8 + rr;
            float a = ps[row * 64 + lane];
            float b = ps[row * 64 + lane + 32];
            float mx = fmaxf(a, b);
            #pragma unroll
            for (int off = 16; off > 0; off >>= 1)
                mx = fmaxf(mx, __shfl_xor_sync(0xffffffffu, mx, off));
            float ea = __expf(a - mx), eb = __expf(b - mx);
            float s = ea + eb;
            #pragma unroll
            for (int off = 16; off > 0; off >>= 1)
                s += __shfl_xor_sync(0xffffffffu, s, off);
            float inv = 1.0f / s;
            ps[row * 64 + lane]      = ea * inv;
            ps[row * 64 + lane + 32] = eb * inv;
        }
    }
    __syncthreads();

    // P @ V
    float o[4][4] = {};
    #pragma unroll 4
    for (int m = 0; m < 64; m++) {
        float pv[4], vv[4];
        #pragma unroll
        for (int i = 0; i < 4; i++) pv[i] = ps[(ty * 4 + i) * 64 + m];
        #pragma unroll
        for (int j = 0; j < 4; j++) vv[j] = vs[m * 64 + tx * 4 + j];
        #pragma unroll
        for (int i = 0; i < 4; i++)
            #pragma unroll
            for (int j = 0; j < 4; j++)
                o[i][j] = fmaf(pv[i], vv[j], o[i][j]);
    }
    #pragma unroll
    for (int i = 0; i < 4; i++) {
        int n = ty * 4 + i;
        float4 v4 = make_float4(o[i][0], o[i][1], o[i][2], o[i][3]);
        *(float4*)(out + ((size_t)(win * 64 + n)) * CDIM + head * HD + tx * 4) = v4;
    }
}

// ---------------- launch ----------------
extern "C" void kernel_launch(void* const* d_in, const int* in_sizes, int n_in,
                              void* d_out, int out_size)
{
    const float* x      = (const float*)d_in[0];
    const float* ln1_g  = (const float*)d_in[1];
    const float* ln1_b  = (const float*)d_in[2];
    const float* qkv_w  = (const float*)d_in[3];
    const float* qkv_b  = (const float*)d_in[4];
    const float* proj_w = (const float*)d_in[5];
    const float* proj_b = (const float*)d_in[6];
    const float* ln2_g  = (const float*)d_in[7];
    const float* ln2_b  = (const float*)d_in[8];
    const float* ffn_w1 = (const float*)d_in[9];
    const float* ffn_b1 = (const float*)d_in[10];
    const float* ffn_w2 = (const float*)d_in[11];
    const float* ffn_b2 = (const float*)d_in[12];
    float* out = (float*)d_out;

    void *p;
    cudaGetSymbolAddress(&p, g_y1);   float* y1   = (float*)p;
    cudaGetSymbolAddress(&p, g_qkv);  float* qkvb = (float*)p;
    cudaGetSymbolAddress(&p, g_attn); float* attn = (float*)p;
    cudaGetSymbolAddress(&p, g_xo);   float* xo   = (float*)p;
    cudaGetSymbolAddress(&p, g_y2);   float* y2   = (float*)p;
    cudaGetSymbolAddress(&p, g_hid);  float* hid  = (float*)p;

    const int smem_attn = (2 * 64 * 65 + 64 * 64) * 4;   // 49664 B
    cudaFuncSetAttribute(attn_kernel, cudaFuncAttributeMaxDynamicSharedMemorySize,
                         smem_attn);

    // 1) LN1 with shift+window gather (window-ordered output)
    ln_kernel<<<TOK, 256>>>(x, ln1_g, ln1_b, y1, 1);

    // 2) QKV GEMM: [65536,512] @ [512,1536]
    gemm_kernel<EPI_NONE><<<dim3(QKVN / BN, TOK / BM), 256>>>(
        y1, qkv_w, qkv_b, nullptr, qkvb, TOK, QKVN, CDIM);

    // 3) attention per (window, head)
    attn_kernel<<<NWIN * NHEAD, 256, smem_attn>>>(qkvb, attn);

    // 4) proj GEMM + residual(x) + scatter to natural layout
    gemm_kernel<EPI_RES_MAP><<<dim3(CDIM / BN, TOK / BM), 256>>>(
        attn, proj_w, proj_b, x, xo, TOK, CDIM, CDIM);

    // 5) LN2 (natural layout)
    ln_kernel<<<TOK, 256>>>(xo, ln2_g, ln2_b, y2, 0);

    // 6) FFN1 + exact GELU: [65536,512] @ [512,2048]
    gemm_kernel<EPI_GELU><<<dim3(HIDN / BN, TOK / BM), 256>>>(
        y2, ffn_w1, ffn_b1, nullptr, hid, TOK, HIDN, CDIM);

    // 7) FFN2 + residual(xo): [65536,2048] @ [2048,512] -> d_out
    gemm_kernel<EPI_RES_NAT><<<dim3(CDIM / BN, TOK / BM), 256>>>(
        hid, ffn_w2, ffn_b2, xo, out, TOK, CDIM, HIDN);
}

// round 3
// speedup vs baseline: 2.0717x; 2.0717x over previous
#include <cuda_runtime.h>
#include <cuda_bf16.h>
#include <cstdint>
#include <math.h>

// ---------------- problem constants ----------------
#define TOK   65536          // 2*32*32*32 tokens
#define CDIM  512
#define QKVN  1536
#define HIDN  2048
#define NWIN  1024           // windows total (2 * 8^3)
#define NHEAD 8
#define HD    64

// ---------------- helpers ----------------
__device__ __forceinline__ uint32_t smem_to_u32(const void* p) {
    uint32_t a;
    asm("{ .reg .u64 t; cvta.to.shared.u64 t, %1; cvt.u32.u64 %0, t; }" : "=r"(a) : "l"(p));
    return a;
}

#define CP_ASYNC16(dst, src) \
    asm volatile("cp.async.cg.shared.global [%0], [%1], 16;" :: "r"(dst), "l"(src))
#define CP_COMMIT() asm volatile("cp.async.commit_group;" ::: "memory")
#define CP_WAIT0()  asm volatile("cp.async.wait_group 0;" ::: "memory")

#define LDSM_X4(r0, r1, r2, r3, addr) \
    asm volatile("ldmatrix.sync.aligned.m8n8.x4.shared.b16 {%0,%1,%2,%3}, [%4];" \
                 : "=r"(r0), "=r"(r1), "=r"(r2), "=r"(r3) : "r"(addr))

__device__ __forceinline__ void mma_bf16(float* c, const uint32_t* a, const uint32_t* b) {
    asm volatile(
        "mma.sync.aligned.m16n8k16.row.col.f32.bf16.bf16.f32 "
        "{%0,%1,%2,%3}, {%4,%5,%6,%7}, {%8,%9}, {%0,%1,%2,%3};"
        : "+f"(c[0]), "+f"(c[1]), "+f"(c[2]), "+f"(c[3])
        : "r"(a[0]), "r"(a[1]), "r"(a[2]), "r"(a[3]), "r"(b[0]), "r"(b[1]));
}

// ---------------- scratch (static device memory) ----------------
__device__ float g_y1  [(size_t)TOK * CDIM];
__device__ float g_qkv [(size_t)TOK * QKVN];
__device__ float g_attn[(size_t)TOK * CDIM];
__device__ float g_xo  [(size_t)TOK * CDIM];
__device__ float g_y2  [(size_t)TOK * CDIM];
__device__ float g_hid [(size_t)TOK * HIDN];

// weight transposed+split buffers: [N, K] bf16 hi/lo
__device__ __nv_bfloat16 g_wqkv_hi[(size_t)QKVN * CDIM];
__device__ __nv_bfloat16 g_wqkv_lo[(size_t)QKVN * CDIM];
__device__ __nv_bfloat16 g_wprj_hi[(size_t)CDIM * CDIM];
__device__ __nv_bfloat16 g_wprj_lo[(size_t)CDIM * CDIM];
__device__ __nv_bfloat16 g_w1_hi  [(size_t)HIDN * CDIM];
__device__ __nv_bfloat16 g_w1_lo  [(size_t)HIDN * CDIM];
__device__ __nv_bfloat16 g_w2_hi  [(size_t)CDIM * HIDN];
__device__ __nv_bfloat16 g_w2_lo  [(size_t)CDIM * HIDN];

// window-ordered row r -> natural token index t
__device__ __forceinline__ int wr2t(int r) {
    int n   = r & 63;
    int win = r >> 6;
    int ww  = win & 7, wh = (win >> 3) & 7, wd = (win >> 6) & 7, b = win >> 9;
    int zw  = n & 3,  zh = (n >> 2) & 3,  zd = n >> 4;
    int d = (wd * 4 + zd + 2) & 31;
    int h = (wh * 4 + zh + 2) & 31;
    int w = (ww * 4 + zw + 2) & 31;
    return ((b * 32 + d) * 32 + h) * 32 + w;
}

__device__ __forceinline__ float gelu_exact(float v) {
    return 0.5f * v * (1.0f + erff(v * 0.70710678118654752f));
}

// ---------------- weight transpose + bf16 split ----------------
__global__ __launch_bounds__(256)
void wsplit_kernel(const float* __restrict__ W, int K, int N,
                   __nv_bfloat16* __restrict__ Whi, __nv_bfloat16* __restrict__ Wlo)
{
    __shared__ float tile[32][33];
    int n0 = blockIdx.x * 32, k0 = blockIdx.y * 32;
    int tx = threadIdx.x & 31, ty = threadIdx.x >> 5;   // 32 x 8
    #pragma unroll
    for (int r = 0; r < 4; r++) {
        int kk = ty + r * 8;
        tile[kk][tx] = W[(size_t)(k0 + kk) * N + n0 + tx];
    }
    __syncthreads();
    #pragma unroll
    for (int r = 0; r < 4; r++) {
        int nn = ty + r * 8;
        float v = tile[tx][nn];
        __nv_bfloat16 h = __float2bfloat16(v);
        float lo = v - __bfloat162float(h);
        size_t o = (size_t)(n0 + nn) * K + k0 + tx;
        Whi[o] = h;
        Wlo[o] = __float2bfloat16(lo);
    }
}

// ---------------- LayerNorm ----------------
__global__ __launch_bounds__(256)
void ln_kernel(const float* __restrict__ X, const float* __restrict__ gam,
               const float* __restrict__ bet, float* __restrict__ Y, int gather)
{
    __shared__ float red[16];
    int r   = blockIdx.x;
    int src = gather ? wr2t(r) : r;
    const float* xr = X + (size_t)src * CDIM;
    int t = threadIdx.x;
    float v0 = xr[t], v1 = xr[t + 256];
    float s = v0 + v1;
    float q = v0 * v0 + v1 * v1;
    #pragma unroll
    for (int off = 16; off > 0; off >>= 1) {
        s += __shfl_xor_sync(0xffffffffu, s, off);
        q += __shfl_xor_sync(0xffffffffu, q, off);
    }
    int w = t >> 5, lane = t & 31;
    if (lane == 0) { red[w] = s; red[8 + w] = q; }
    __syncthreads();
    if (w == 0) {
        float s2 = (lane < 8) ? red[lane] : 0.f;
        float q2 = (lane < 8) ? red[8 + lane] : 0.f;
        #pragma unroll
        for (int off = 4; off > 0; off >>= 1) {
            s2 += __shfl_xor_sync(0xffffffffu, s2, off);
            q2 += __shfl_xor_sync(0xffffffffu, q2, off);
        }
        if (lane == 0) { red[0] = s2; red[1] = q2; }
    }
    __syncthreads();
    float mean = red[0] * (1.0f / CDIM);
    float var  = red[1] * (1.0f / CDIM) - mean * mean;
    float rstd = rsqrtf(var + 1e-5f);
    float* yr = Y + (size_t)r * CDIM;
    yr[t]       = (v0 - mean) * rstd * gam[t]       + bet[t];
    yr[t + 256] = (v1 - mean) * rstd * gam[t + 256] + bet[t + 256];
}

// ---------------- tensor-core GEMM via mma.sync (bf16 3-term split) -------
// C[M,N] = A[M,K] @ B[K,N] + bias;  Bhi/Blo pre-transposed [N,K] bf16.
// CTA 128x128, 8 warps in 2(M)x4(N), warp tile 64x32, BK=32.
// smem per buffer: Ah,Al,Bh,Bl each 128 rows x 80B (32 bf16 + 16B pad) = 10240B.
#define EPI_NONE    0
#define EPI_GELU    1
#define EPI_RES_MAP 2
#define EPI_RES_NAT 3

#define ROWPITCH 80
#define REG_A    0
#define REG_AL   10240
#define REG_B    20480
#define REG_BL   30720
#define BUFSZ    40960
#define GT_SMEM  (2 * BUFSZ)

template<int EPI>
__global__ __launch_bounds__(256, 1)
void gemm_mma(const float* __restrict__ A, const __nv_bfloat16* __restrict__ Bhi,
              const __nv_bfloat16* __restrict__ Blo, const float* __restrict__ bias,
              const float* __restrict__ R, float* __restrict__ C, int M, int N, int K)
{
    extern __shared__ char sm[];
    const uint32_t smb = smem_to_u32(sm);
    const int tid  = threadIdx.x;
    const int wid  = tid >> 5, lane = tid & 31;
    const int wm   = wid & 1,  wn   = wid >> 1;
    const int row0 = blockIdx.y * 128, col0 = blockIdx.x * 128;

    // loader indexing: seg s covers row = s>>2, k8 = (s&3)*8 (8 elements)
    const int s0row = tid >> 2, s0k8 = (tid & 3) * 8;         // seg = tid
    const int s1row = s0row + 64;                              // seg = tid + 256

    // ldmatrix lane addressing
    const int g = lane >> 3, r = lane & 7;
    const uint32_t aoff = (uint32_t)((wm * 64 + (g & 1) * 8 + r) * ROWPITCH + (g >> 1) * 16);
    const uint32_t boff = (uint32_t)(((g >> 1) * 8 + r + wn * 32) * ROWPITCH + (g & 1) * 16);

    float acc[4][4][4];
    #pragma unroll
    for (int i = 0; i < 4; i++)
        #pragma unroll
        for (int j = 0; j < 4; j++)
            #pragma unroll
            for (int e = 0; e < 4; e++) acc[i][j][e] = 0.f;

    const int NC = K >> 5;

    // ---- chunk 0 loads ----
    {
        uint32_t bb = smb + REG_B;
        size_t gh = (size_t)(col0 + s0row) * K + s0k8;
        CP_ASYNC16(bb + s0row * ROWPITCH + s0k8 * 2, Bhi + gh);
        CP_ASYNC16(bb + REG_BL - REG_B + s0row * ROWPITCH + s0k8 * 2, Blo + gh);
        size_t gh2 = (size_t)(col0 + s1row) * K + s0k8;
        CP_ASYNC16(bb + s1row * ROWPITCH + s0k8 * 2, Bhi + gh2);
        CP_ASYNC16(bb + REG_BL - REG_B + s1row * ROWPITCH + s0k8 * 2, Blo + gh2);
        CP_COMMIT();
        #pragma unroll
        for (int i = 0; i < 2; i++) {
            int rr = (i == 0) ? s0row : s1row;
            const float* ap = A + (size_t)(row0 + rr) * K + s0k8;
            float4 f0 = *(const float4*)ap;
            float4 f1 = *(const float4*)(ap + 4);
            float fv[8] = {f0.x, f0.y, f0.z, f0.w, f1.x, f1.y, f1.z, f1.w};
            union { uint4 q; __nv_bfloat16 b[8]; } hv, lv;
            #pragma unroll
            for (int e = 0; e < 8; e++) {
                __nv_bfloat16 h = __float2bfloat16(fv[e]);
                hv.b[e] = h;
                lv.b[e] = __float2bfloat16(fv[e] - __bfloat162float(h));
            }
            char* base = sm + rr * ROWPITCH + s0k8 * 2;
            *(uint4*)(base + REG_A)  = hv.q;
            *(uint4*)(base + REG_AL) = lv.q;
        }
        CP_WAIT0();
        __syncthreads();
    }

    for (int c = 0; c < NC; c++) {
        const int buf = c & 1;
        const uint32_t ab = smb + buf * BUFSZ;
        const int kn = (c + 1) * 32;
        float4 pf0, pf1, pf2, pf3;

        if (c + 1 < NC) {
            // B next chunk via cp.async
            uint32_t bb = smb + (buf ^ 1) * BUFSZ + REG_B;
            size_t gh = (size_t)(col0 + s0row) * K + kn + s0k8;
            CP_ASYNC16(bb + s0row * ROWPITCH + s0k8 * 2, Bhi + gh);
            CP_ASYNC16(bb + 10240 + s0row * ROWPITCH + s0k8 * 2, Blo + gh);
            size_t gh2 = (size_t)(col0 + s1row) * K + kn + s0k8;
            CP_ASYNC16(bb + s1row * ROWPITCH + s0k8 * 2, Bhi + gh2);
            CP_ASYNC16(bb + 10240 + s1row * ROWPITCH + s0k8 * 2, Blo + gh2);
            CP_COMMIT();
            // A next chunk global -> regs (stores after compute)
            const float* ap0 = A + (size_t)(row0 + s0row) * K + kn + s0k8;
            const float* ap1 = A + (size_t)(row0 + s1row) * K + kn + s0k8;
            pf0 = *(const float4*)ap0;  pf1 = *(const float4*)(ap0 + 4);
            pf2 = *(const float4*)ap1;  pf3 = *(const float4*)(ap1 + 4);
        }

        // ---- compute current chunk: 2 k16 steps ----
        #pragma unroll
        for (int s = 0; s < 2; s++) {
            uint32_t ah[4][4], al[4][4], bh[4][2], bl[4][2];
            #pragma unroll
            for (int mi = 0; mi < 4; mi++) {
                uint32_t addr = ab + aoff + mi * (16 * ROWPITCH) + s * 32;
                LDSM_X4(ah[mi][0], ah[mi][1], ah[mi][2], ah[mi][3], addr + REG_A);
                LDSM_X4(al[mi][0], al[mi][1], al[mi][2], al[mi][3], addr + REG_AL);
            }
            #pragma unroll
            for (int nj = 0; nj < 2; nj++) {
                uint32_t addr = ab + boff + nj * (16 * ROWPITCH) + s * 32;
                LDSM_X4(bh[nj*2][0], bh[nj*2][1], bh[nj*2+1][0], bh[nj*2+1][1], addr + REG_B);
                LDSM_X4(bl[nj*2][0], bl[nj*2][1], bl[nj*2+1][0], bl[nj*2+1][1], addr + REG_BL);
            }
            #pragma unroll
            for (int mi = 0; mi < 4; mi++)
                #pragma unroll
                for (int ni = 0; ni < 4; ni++) {
                    mma_bf16(acc[mi][ni], ah[mi], bh[ni]);
                    mma_bf16(acc[mi][ni], al[mi], bh[ni]);
                    mma_bf16(acc[mi][ni], ah[mi], bl[ni]);
                }
        }

        if (c + 1 < NC) {
            // store prefetched A (converted) into other buffer
            char* ob = sm + (buf ^ 1) * BUFSZ;
            float fv[8] = {pf0.x, pf0.y, pf0.z, pf0.w, pf1.x, pf1.y, pf1.z, pf1.w};
            union { uint4 q; __nv_bfloat16 b[8]; } hv, lv;
            #pragma unroll
            for (int e = 0; e < 8; e++) {
                __nv_bfloat16 h = __float2bfloat16(fv[e]);
                hv.b[e] = h;
                lv.b[e] = __float2bfloat16(fv[e] - __bfloat162float(h));
            }
            *(uint4*)(ob + REG_A  + s0row * ROWPITCH + s0k8 * 2) = hv.q;
            *(uint4*)(ob + REG_AL + s0row * ROWPITCH + s0k8 * 2) = lv.q;
            float fw[8] = {pf2.x, pf2.y, pf2.z, pf2.w, pf3.x, pf3.y, pf3.z, pf3.w};
            #pragma unroll
            for (int e = 0; e < 8; e++) {
                __nv_bfloat16 h = __float2bfloat16(fw[e]);
                hv.b[e] = h;
                lv.b[e] = __float2bfloat16(fw[e] - __bfloat162float(h));
            }
            *(uint4*)(ob + REG_A  + s1row * ROWPITCH + s0k8 * 2) = hv.q;
            *(uint4*)(ob + REG_AL + s1row * ROWPITCH + s0k8 * 2) = lv.q;
            CP_WAIT0();
        }
        __syncthreads();
    }

    // ---- epilogue ----
    const int qrow = lane >> 2;
    const int qcol = (lane & 3) * 2;
    #pragma unroll
    for (int mi = 0; mi < 4; mi++) {
        int gr0 = row0 + wm * 64 + mi * 16 + qrow;
        int gr1 = gr0 + 8;
        int or0 = (EPI == EPI_RES_MAP) ? wr2t(gr0) : gr0;
        int or1 = (EPI == EPI_RES_MAP) ? wr2t(gr1) : gr1;
        #pragma unroll
        for (int ni = 0; ni < 4; ni++) {
            int col = col0 + wn * 32 + ni * 8 + qcol;
            float b0 = bias[col], b1 = bias[col + 1];
            float v00 = acc[mi][ni][0] + b0, v01 = acc[mi][ni][1] + b1;
            float v10 = acc[mi][ni][2] + b0, v11 = acc[mi][ni][3] + b1;
            if (EPI == EPI_GELU) {
                v00 = gelu_exact(v00); v01 = gelu_exact(v01);
                v10 = gelu_exact(v10); v11 = gelu_exact(v11);
            }
            if (EPI == EPI_RES_MAP || EPI == EPI_RES_NAT) {
                float2 r0v = *(const float2*)(R + (size_t)or0 * N + col);
                float2 r1v = *(const float2*)(R + (size_t)or1 * N + col);
                v00 += r0v.x; v01 += r0v.y; v10 += r1v.x; v11 += r1v.y;
            }
            *(float2*)(C + (size_t)or0 * N + col) = make_float2(v00, v01);
            *(float2*)(C + (size_t)or1 * N + col) = make_float2(v10, v11);
        }
    }
}

// ---------------- windowed attention: one block per (window, head) -------
__global__ __launch_bounds__(256)
void attn_kernel(const float* __restrict__ qkv, float* __restrict__ out)
{
    extern __shared__ float smf[];
    float* qts = smf;
    float* kts = smf + 64 * 65;
    float* vs  = smf + 2 * 64 * 65;
    float* ps  = smf;

    const int tid  = threadIdx.x;
    const int win  = blockIdx.x >> 3;
    const int head = blockIdx.x & 7;
    const size_t base0 = (size_t)win * 64 * QKVN + head * HD;

    for (int e = tid; e < 4096; e += 256) {
        int n = e >> 6, dd = e & 63;
        size_t base = base0 + (size_t)n * QKVN + dd;
        qts[dd * 65 + n] = qkv[base];
        kts[dd * 65 + n] = qkv[base + 512];
        vs[n * 64 + dd]  = qkv[base + 1024];
    }
    __syncthreads();

    const int tx = tid & 15, ty = tid >> 4;
    float acc[4][4] = {};
    #pragma unroll 4
    for (int dd = 0; dd < 64; dd++) {
        float qa[4], kb[4];
        #pragma unroll
        for (int i = 0; i < 4; i++) qa[i] = qts[dd * 65 + ty * 4 + i];
        #pragma unroll
        for (int j = 0; j < 4; j++) kb[j] = kts[dd * 65 + tx * 4 + j];
        #pragma unroll
        for (int i = 0; i < 4; i++)
            #pragma unroll
            for (int j = 0; j < 4; j++)
                acc[i][j] = fmaf(qa[i], kb[j], acc[i][j]);
    }
    __syncthreads();
    #pragma unroll
    for (int i = 0; i < 4; i++)
        #pragma unroll
        for (int j = 0; j < 4; j++)
            ps[(ty * 4 + i) * 64 + tx * 4 + j] = acc[i][j] * 0.125f;
    __syncthreads();

    {
        int w = tid >> 5, lane = tid & 31;
        #pragma unroll
        for (int rr = 0; rr < 8; rr++) {
            int row = w * 8 + rr;
            float a = ps[row * 64 + lane];
            float b = ps[row * 64 + lane + 32];
            float mx = fmaxf(a, b);
            #pragma unroll
            for (int off = 16; off > 0; off >>= 1)
                mx = fmaxf(mx, __shfl_xor_sync(0xffffffffu, mx, off));
            float ea = __expf(a - mx), eb = __expf(b - mx);
            float s = ea + eb;
            #pragma unroll
            for (int off = 16; off > 0; off >>= 1)
                s += __shfl_xor_sync(0xffffffffu, s, off);
            float inv = 1.0f / s;
            ps[row * 64 + lane]      = ea * inv;
            ps[row * 64 + lane + 32] = eb * inv;
        }
    }
    __syncthreads();

    float o[4][4] = {};
    #pragma unroll 4
    for (int m = 0; m < 64; m++) {
        float pv[4], vv[4];
        #pragma unroll
        for (int i = 0; i < 4; i++) pv[i] = ps[(ty * 4 + i) * 64 + m];
        #pragma unroll
        for (int j = 0; j < 4; j++) vv[j] = vs[m * 64 + tx * 4 + j];
        #pragma unroll
        for (int i = 0; i < 4; i++)
            #pragma unroll
            for (int j = 0; j < 4; j++)
                o[i][j] = fmaf(pv[i], vv[j], o[i][j]);
    }
    #pragma unroll
    for (int i = 0; i < 4; i++) {
        int n = ty * 4 + i;
        float4 v4 = make_float4(o[i][0], o[i][1], o[i][2], o[i][3]);
        *(float4*)(out + ((size_t)(win * 64 + n)) * CDIM + head * HD + tx * 4) = v4;
    }
}

// ---------------- launch ----------------
extern "C" void kernel_launch(void* const* d_in, const int* in_sizes, int n_in,
                              void* d_out, int out_size)
{
    const float* x      = (const float*)d_in[0];
    const float* ln1_g  = (const float*)d_in[1];
    const float* ln1_b  = (const float*)d_in[2];
    const float* qkv_w  = (const float*)d_in[3];
    const float* qkv_b  = (const float*)d_in[4];
    const float* proj_w = (const float*)d_in[5];
    const float* proj_b = (const float*)d_in[6];
    const float* ln2_g  = (const float*)d_in[7];
    const float* ln2_b  = (const float*)d_in[8];
    const float* ffn_w1 = (const float*)d_in[9];
    const float* ffn_b1 = (const float*)d_in[10];
    const float* ffn_w2 = (const float*)d_in[11];
    const float* ffn_b2 = (const float*)d_in[12];
    float* out = (float*)d_out;

    void* p;
    cudaGetSymbolAddress(&p, g_y1);   float* y1   = (float*)p;
    cudaGetSymbolAddress(&p, g_qkv);  float* qkvb = (float*)p;
    cudaGetSymbolAddress(&p, g_attn); float* attn = (float*)p;
    cudaGetSymbolAddress(&p, g_xo);   float* xo   = (float*)p;
    cudaGetSymbolAddress(&p, g_y2);   float* y2   = (float*)p;
    cudaGetSymbolAddress(&p, g_hid);  float* hid  = (float*)p;
    __nv_bfloat16 *wqh, *wql, *wph, *wpl, *w1h, *w1l, *w2h, *w2l;
    cudaGetSymbolAddress(&p, g_wqkv_hi); wqh = (__nv_bfloat16*)p;
    cudaGetSymbolAddress(&p, g_wqkv_lo); wql = (__nv_bfloat16*)p;
    cudaGetSymbolAddress(&p, g_wprj_hi); wph = (__nv_bfloat16*)p;
    cudaGetSymbolAddress(&p, g_wprj_lo); wpl = (__nv_bfloat16*)p;
    cudaGetSymbolAddress(&p, g_w1_hi);   w1h = (__nv_bfloat16*)p;
    cudaGetSymbolAddress(&p, g_w1_lo);   w1l = (__nv_bfloat16*)p;
    cudaGetSymbolAddress(&p, g_w2_hi);   w2h = (__nv_bfloat16*)p;
    cudaGetSymbolAddress(&p, g_w2_lo);   w2l = (__nv_bfloat16*)p;

    const int smem_attn = (2 * 64 * 65 + 64 * 64) * 4;
    cudaFuncSetAttribute(attn_kernel, cudaFuncAttributeMaxDynamicSharedMemorySize, smem_attn);
    cudaFuncSetAttribute(gemm_mma<EPI_NONE>,    cudaFuncAttributeMaxDynamicSharedMemorySize, GT_SMEM);
    cudaFuncSetAttribute(gemm_mma<EPI_GELU>,    cudaFuncAttributeMaxDynamicSharedMemorySize, GT_SMEM);
    cudaFuncSetAttribute(gemm_mma<EPI_RES_MAP>, cudaFuncAttributeMaxDynamicSharedMemorySize, GT_SMEM);
    cudaFuncSetAttribute(gemm_mma<EPI_RES_NAT>, cudaFuncAttributeMaxDynamicSharedMemorySize, GT_SMEM);

    // 0) weight transpose + bf16 split
    wsplit_kernel<<<dim3(QKVN / 32, CDIM / 32), 256>>>(qkv_w,  CDIM, QKVN, wqh, wql);
    wsplit_kernel<<<dim3(CDIM / 32, CDIM / 32), 256>>>(proj_w, CDIM, CDIM, wph, wpl);
    wsplit_kernel<<<dim3(HIDN / 32, CDIM / 32), 256>>>(ffn_w1, CDIM, HIDN, w1h, w1l);
    wsplit_kernel<<<dim3(CDIM / 32, HIDN / 32), 256>>>(ffn_w2, HIDN, CDIM, w2h, w2l);

    // 1) LN1 with shift+window gather
    ln_kernel<<<TOK, 256>>>(x, ln1_g, ln1_b, y1, 1);

    // 2) QKV GEMM
    gemm_mma<EPI_NONE><<<dim3(QKVN / 128, TOK / 128), 256, GT_SMEM>>>(
        y1, wqh, wql, qkv_b, nullptr, qkvb, TOK, QKVN, CDIM);

    // 3) attention
    attn_kernel<<<NWIN * NHEAD, 256, smem_attn>>>(qkvb, attn);

    // 4) proj GEMM + residual(x) + scatter to natural layout
    gemm_mma<EPI_RES_MAP><<<dim3(CDIM / 128, TOK / 128), 256, GT_SMEM>>>(
        attn, wph, wpl, proj_b, x, xo, TOK, CDIM, CDIM);

    // 5) LN2
    ln_kernel<<<TOK, 256>>>(xo, ln2_g, ln2_b, y2, 0);

    // 6) FFN1 + GELU
    gemm_mma<EPI_GELU><<<dim3(HIDN / 128, TOK / 128), 256, GT_SMEM>>>(
        y2, w1h, w1l, ffn_b1, nullptr, hid, TOK, HIDN, CDIM);

    // 7) FFN2 + residual(xo) -> out
    gemm_mma<EPI_RES_NAT><<<dim3(CDIM / 128, TOK / 128), 256, GT_SMEM>>>(
        hid, w2h, w2l, ffn_b2, xo, out, TOK, CDIM, HIDN);
}

// round 4
// speedup vs baseline: 2.4325x; 1.1742x over previous
#include <cuda_runtime.h>
#include <cuda_bf16.h>
#include <cstdint>
#include <math.h>

// ---------------- problem constants ----------------
#define TOK   65536          // 2*32*32*32 tokens
#define CDIM  512
#define QKVN  1536
#define HIDN  2048
#define NWIN  1024           // windows total (2 * 8^3)
#define NHEAD 8
#define HD    64

// ---------------- helpers ----------------
__device__ __forceinline__ uint32_t smem_to_u32(const void* p) {
    uint32_t a;
    asm("{ .reg .u64 t; cvta.to.shared.u64 t, %1; cvt.u32.u64 %0, t; }" : "=r"(a) : "l"(p));
    return a;
}

#define CP_ASYNC16(dst, src) \
    asm volatile("cp.async.cg.shared.global [%0], [%1], 16;" :: "r"(dst), "l"(src))
#define CP_COMMIT() asm volatile("cp.async.commit_group;" ::: "memory")
#define CP_WAIT0()  asm volatile("cp.async.wait_group 0;" ::: "memory")

#define LDSM_X4(r0, r1, r2, r3, addr) \
    asm volatile("ldmatrix.sync.aligned.m8n8.x4.shared.b16 {%0,%1,%2,%3}, [%4];" \
                 : "=r"(r0), "=r"(r1), "=r"(r2), "=r"(r3) : "r"(addr))

__device__ __forceinline__ void mma_bf16(float* c, const uint32_t* a, const uint32_t* b) {
    asm volatile(
        "mma.sync.aligned.m16n8k16.row.col.f32.bf16.bf16.f32 "
        "{%0,%1,%2,%3}, {%4,%5,%6,%7}, {%8,%9}, {%0,%1,%2,%3};"
        : "+f"(c[0]), "+f"(c[1]), "+f"(c[2]), "+f"(c[3])
        : "r"(a[0]), "r"(a[1]), "r"(a[2]), "r"(a[3]), "r"(b[0]), "r"(b[1]));
}

__device__ __forceinline__ void split2(float v, __nv_bfloat16& h, __nv_bfloat16& l) {
    h = __float2bfloat16(v);
    l = __float2bfloat16(v - __bfloat162float(h));
}

// ---------------- scratch (static device memory) ----------------
__device__ float g_qkv [(size_t)TOK * QKVN];                 // fp32 (attention input)
__device__ float g_xo  [(size_t)TOK * CDIM];                 // fp32 residual base
// pre-split bf16 activations (GEMM A-operands)
__device__ __nv_bfloat16 g_y1h [(size_t)TOK * CDIM];
__device__ __nv_bfloat16 g_y1l [(size_t)TOK * CDIM];
__device__ __nv_bfloat16 g_ath [(size_t)TOK * CDIM];
__device__ __nv_bfloat16 g_atl [(size_t)TOK * CDIM];
__device__ __nv_bfloat16 g_y2h [(size_t)TOK * CDIM];
__device__ __nv_bfloat16 g_y2l [(size_t)TOK * CDIM];
__device__ __nv_bfloat16 g_hidh[(size_t)TOK * HIDN];
__device__ __nv_bfloat16 g_hidl[(size_t)TOK * HIDN];
// weight transposed+split buffers: [N, K] bf16 hi/lo
__device__ __nv_bfloat16 g_wqkv_hi[(size_t)QKVN * CDIM];
__device__ __nv_bfloat16 g_wqkv_lo[(size_t)QKVN * CDIM];
__device__ __nv_bfloat16 g_wprj_hi[(size_t)CDIM * CDIM];
__device__ __nv_bfloat16 g_wprj_lo[(size_t)CDIM * CDIM];
__device__ __nv_bfloat16 g_w1_hi  [(size_t)HIDN * CDIM];
__device__ __nv_bfloat16 g_w1_lo  [(size_t)HIDN * CDIM];
__device__ __nv_bfloat16 g_w2_hi  [(size_t)CDIM * HIDN];
__device__ __nv_bfloat16 g_w2_lo  [(size_t)CDIM * HIDN];

// window-ordered row r -> natural token index t
__device__ __forceinline__ int wr2t(int r) {
    int n   = r & 63;
    int win = r >> 6;
    int ww  = win & 7, wh = (win >> 3) & 7, wd = (win >> 6) & 7, b = win >> 9;
    int zw  = n & 3,  zh = (n >> 2) & 3,  zd = n >> 4;
    int d = (wd * 4 + zd + 2) & 31;
    int h = (wh * 4 + zh + 2) & 31;
    int w = (ww * 4 + zw + 2) & 31;
    return ((b * 32 + d) * 32 + h) * 32 + w;
}

__device__ __forceinline__ float gelu_exact(float v) {
    return 0.5f * v * (1.0f + erff(v * 0.70710678118654752f));
}

// ---------------- weight transpose + bf16 split ----------------
__global__ __launch_bounds__(256)
void wsplit_kernel(const float* __restrict__ W, int K, int N,
                   __nv_bfloat16* __restrict__ Whi, __nv_bfloat16* __restrict__ Wlo)
{
    __shared__ float tile[32][33];
    int n0 = blockIdx.x * 32, k0 = blockIdx.y * 32;
    int tx = threadIdx.x & 31, ty = threadIdx.x >> 5;   // 32 x 8
    #pragma unroll
    for (int r = 0; r < 4; r++) {
        int kk = ty + r * 8;
        tile[kk][tx] = W[(size_t)(k0 + kk) * N + n0 + tx];
    }
    __syncthreads();
    #pragma unroll
    for (int r = 0; r < 4; r++) {
        int nn = ty + r * 8;
        float v = tile[tx][nn];
        __nv_bfloat16 h, l;
        split2(v, h, l);
        size_t o = (size_t)(n0 + nn) * K + k0 + tx;
        Whi[o] = h;
        Wlo[o] = l;
    }
}

// ---------------- LayerNorm -> split bf16 hi/lo ----------------
__global__ __launch_bounds__(256)
void ln_kernel(const float* __restrict__ X, const float* __restrict__ gam,
               const float* __restrict__ bet,
               __nv_bfloat16* __restrict__ Yh, __nv_bfloat16* __restrict__ Yl,
               int gather)
{
    __shared__ float red[16];
    int r   = blockIdx.x;
    int src = gather ? wr2t(r) : r;
    const float* xr = X + (size_t)src * CDIM;
    int t = threadIdx.x;
    float v0 = xr[t], v1 = xr[t + 256];
    float s = v0 + v1;
    float q = v0 * v0 + v1 * v1;
    #pragma unroll
    for (int off = 16; off > 0; off >>= 1) {
        s += __shfl_xor_sync(0xffffffffu, s, off);
        q += __shfl_xor_sync(0xffffffffu, q, off);
    }
    int w = t >> 5, lane = t & 31;
    if (lane == 0) { red[w] = s; red[8 + w] = q; }
    __syncthreads();
    if (w == 0) {
        float s2 = (lane < 8) ? red[lane] : 0.f;
        float q2 = (lane < 8) ? red[8 + lane] : 0.f;
        #pragma unroll
        for (int off = 4; off > 0; off >>= 1) {
            s2 += __shfl_xor_sync(0xffffffffu, s2, off);
            q2 += __shfl_xor_sync(0xffffffffu, q2, off);
        }
        if (lane == 0) { red[0] = s2; red[1] = q2; }
    }
    __syncthreads();
    float mean = red[0] * (1.0f / CDIM);
    float var  = red[1] * (1.0f / CDIM) - mean * mean;
    float rstd = rsqrtf(var + 1e-5f);
    size_t rb = (size_t)r * CDIM;
    float y0 = (v0 - mean) * rstd * gam[t]       + bet[t];
    float y1 = (v1 - mean) * rstd * gam[t + 256] + bet[t + 256];
    __nv_bfloat16 h, l;
    split2(y0, h, l); Yh[rb + t] = h;       Yl[rb + t] = l;
    split2(y1, h, l); Yh[rb + t + 256] = h; Yl[rb + t + 256] = l;
}

// ---------------- tensor-core GEMM via mma.sync (bf16 3-term split) -------
// C[M,N] = A[M,K] @ B[K,N] + bias;  A pre-split [M,K] hi/lo, B pre-split [N,K] hi/lo.
// CTA 128x128, 8 warps in 2(M)x4(N), warp tile 64x32, BK=32, double buffer.
#define EPI_NONE    0
#define EPI_GELU    1
#define EPI_RES_MAP 2
#define EPI_RES_NAT 3

#define ROWPITCH 80
#define REG_A    0
#define REG_AL   10240
#define REG_B    20480
#define REG_BL   30720
#define BUFSZ    40960
#define GT_SMEM  (2 * BUFSZ)

template<int EPI, int OUTSPLIT>
__global__ __launch_bounds__(256, 2)
void gemm_mma(const __nv_bfloat16* __restrict__ Ahi, const __nv_bfloat16* __restrict__ Alo,
              const __nv_bfloat16* __restrict__ Bhi, const __nv_bfloat16* __restrict__ Blo,
              const float* __restrict__ bias, const float* __restrict__ R,
              float* __restrict__ C, __nv_bfloat16* __restrict__ Chi,
              __nv_bfloat16* __restrict__ Clo, int M, int N, int K)
{
    extern __shared__ char sm[];
    const uint32_t smb = smem_to_u32(sm);
    const int tid  = threadIdx.x;
    const int wid  = tid >> 5, lane = tid & 31;
    const int wm   = wid & 1,  wn   = wid >> 1;
    const int row0 = blockIdx.y * 128, col0 = blockIdx.x * 128;

    const int s0row = tid >> 2, s0k8 = (tid & 3) * 8;   // seg tid
    const int s1row = s0row + 64;                        // seg tid + 256
    const uint32_t so0 = (uint32_t)(s0row * ROWPITCH + s0k8 * 2);
    const uint32_t so1 = (uint32_t)(s1row * ROWPITCH + s0k8 * 2);

    const int g = lane >> 3, r = lane & 7;
    const uint32_t aoff = (uint32_t)((wm * 64 + (g & 1) * 8 + r) * ROWPITCH + (g >> 1) * 16);
    const uint32_t boff = (uint32_t)(((g >> 1) * 8 + r + wn * 32) * ROWPITCH + (g & 1) * 16);

    float acc[4][4][4];
    #pragma unroll
    for (int i = 0; i < 4; i++)
        #pragma unroll
        for (int j = 0; j < 4; j++)
            #pragma unroll
            for (int e = 0; e < 4; e++) acc[i][j][e] = 0.f;

    const int NC = K >> 5;

    // chunk loader (all cp.async)
    auto load_chunk = [&](int kc, int buf) {
        const uint32_t bb = smb + buf * BUFSZ;
        size_t ga0 = (size_t)(row0 + s0row) * K + kc + s0k8;
        size_t ga1 = (size_t)(row0 + s1row) * K + kc + s0k8;
        CP_ASYNC16(bb + REG_A  + so0, Ahi + ga0);
        CP_ASYNC16(bb + REG_AL + so0, Alo + ga0);
        CP_ASYNC16(bb + REG_A  + so1, Ahi + ga1);
        CP_ASYNC16(bb + REG_AL + so1, Alo + ga1);
        size_t gb0 = (size_t)(col0 + s0row) * K + kc + s0k8;
        size_t gb1 = (size_t)(col0 + s1row) * K + kc + s0k8;
        CP_ASYNC16(bb + REG_B  + so0, Bhi + gb0);
        CP_ASYNC16(bb + REG_BL + so0, Blo + gb0);
        CP_ASYNC16(bb + REG_B  + so1, Bhi + gb1);
        CP_ASYNC16(bb + REG_BL + so1, Blo + gb1);
        CP_COMMIT();
    };

    load_chunk(0, 0);
    CP_WAIT0();
    __syncthreads();

    for (int c = 0; c < NC; c++) {
        const int buf = c & 1;
        const uint32_t ab = smb + buf * BUFSZ;

        if (c + 1 < NC) load_chunk((c + 1) * 32, buf ^ 1);

        #pragma unroll
        for (int s = 0; s < 2; s++) {
            uint32_t ah[4][4], al[4][4], bh[4][2], bl[4][2];
            #pragma unroll
            for (int mi = 0; mi < 4; mi++) {
                uint32_t addr = ab + aoff + mi * (16 * ROWPITCH) + s * 32;
                LDSM_X4(ah[mi][0], ah[mi][1], ah[mi][2], ah[mi][3], addr + REG_A);
                LDSM_X4(al[mi][0], al[mi][1], al[mi][2], al[mi][3], addr + REG_AL);
            }
            #pragma unroll
            for (int nj = 0; nj < 2; nj++) {
                uint32_t addr = ab + boff + nj * (16 * ROWPITCH) + s * 32;
                LDSM_X4(bh[nj*2][0], bh[nj*2][1], bh[nj*2+1][0], bh[nj*2+1][1], addr + REG_B);
                LDSM_X4(bl[nj*2][0], bl[nj*2][1], bl[nj*2+1][0], bl[nj*2+1][1], addr + REG_BL);
            }
            #pragma unroll
            for (int mi = 0; mi < 4; mi++)
                #pragma unroll
                for (int ni = 0; ni < 4; ni++) {
                    mma_bf16(acc[mi][ni], ah[mi], bh[ni]);
                    mma_bf16(acc[mi][ni], al[mi], bh[ni]);
                    mma_bf16(acc[mi][ni], ah[mi], bl[ni]);
                }
        }

        if (c + 1 < NC) CP_WAIT0();
        __syncthreads();
    }

    // ---- epilogue ----
    const int qrow = lane >> 2;
    const int qcol = (lane & 3) * 2;
    #pragma unroll
    for (int mi = 0; mi < 4; mi++) {
        int gr0 = row0 + wm * 64 + mi * 16 + qrow;
        int gr1 = gr0 + 8;
        int or0 = (EPI == EPI_RES_MAP) ? wr2t(gr0) : gr0;
        int or1 = (EPI == EPI_RES_MAP) ? wr2t(gr1) : gr1;
        #pragma unroll
        for (int ni = 0; ni < 4; ni++) {
            int col = col0 + wn * 32 + ni * 8 + qcol;
            float b0 = bias[col], b1 = bias[col + 1];
            float v00 = acc[mi][ni][0] + b0, v01 = acc[mi][ni][1] + b1;
            float v10 = acc[mi][ni][2] + b0, v11 = acc[mi][ni][3] + b1;
            if (EPI == EPI_GELU) {
                v00 = gelu_exact(v00); v01 = gelu_exact(v01);
                v10 = gelu_exact(v10); v11 = gelu_exact(v11);
            }
            if (EPI == EPI_RES_MAP || EPI == EPI_RES_NAT) {
                float2 r0v = *(const float2*)(R + (size_t)or0 * N + col);
                float2 r1v = *(const float2*)(R + (size_t)or1 * N + col);
                v00 += r0v.x; v01 += r0v.y; v10 += r1v.x; v11 += r1v.y;
            }
            if (OUTSPLIT) {
                __nv_bfloat16 h0, l0, h1, l1;
                split2(v00, h0, l0); split2(v01, h1, l1);
                *(__nv_bfloat162*)(Chi + (size_t)or0 * N + col) = __nv_bfloat162(h0, h1);
                *(__nv_bfloat162*)(Clo + (size_t)or0 * N + col) = __nv_bfloat162(l0, l1);
                split2(v10, h0, l0); split2(v11, h1, l1);
                *(__nv_bfloat162*)(Chi + (size_t)or1 * N + col) = __nv_bfloat162(h0, h1);
                *(__nv_bfloat162*)(Clo + (size_t)or1 * N + col) = __nv_bfloat162(l0, l1);
            } else {
                *(float2*)(C + (size_t)or0 * N + col) = make_float2(v00, v01);
                *(float2*)(C + (size_t)or1 * N + col) = make_float2(v10, v11);
            }
        }
    }
}

// ---------------- windowed attention: one block per (window, head) -------
__global__ __launch_bounds__(256)
void attn_kernel(const float* __restrict__ qkv,
                 __nv_bfloat16* __restrict__ outh, __nv_bfloat16* __restrict__ outl)
{
    extern __shared__ float smf[];
    float* qts = smf;
    float* kts = smf + 64 * 65;
    float* vs  = smf + 2 * 64 * 65;
    float* ps  = smf;

    const int tid  = threadIdx.x;
    const int win  = blockIdx.x >> 3;
    const int head = blockIdx.x & 7;
    const size_t base0 = (size_t)win * 64 * QKVN + head * HD;

    for (int e = tid; e < 4096; e += 256) {
        int n = e >> 6, dd = e & 63;
        size_t base = base0 + (size_t)n * QKVN + dd;
        qts[dd * 65 + n] = qkv[base];
        kts[dd * 65 + n] = qkv[base + 512];
        vs[n * 64 + dd]  = qkv[base + 1024];
    }
    __syncthreads();

    const int tx = tid & 15, ty = tid >> 4;
    float acc[4][4] = {};
    #pragma unroll 4
    for (int dd = 0; dd < 64; dd++) {
        float qa[4], kb[4];
        #pragma unroll
        for (int i = 0; i < 4; i++) qa[i] = qts[dd * 65 + ty * 4 + i];
        #pragma unroll
        for (int j = 0; j < 4; j++) kb[j] = kts[dd * 65 + tx * 4 + j];
        #pragma unroll
        for (int i = 0; i < 4; i++)
            #pragma unroll
            for (int j = 0; j < 4; j++)
                acc[i][j] = fmaf(qa[i], kb[j], acc[i][j]);
    }
    __syncthreads();
    #pragma unroll
    for (int i = 0; i < 4; i++)
        #pragma unroll
        for (int j = 0; j < 4; j++)
            ps[(ty * 4 + i) * 64 + tx * 4 + j] = acc[i][j] * 0.125f;
    __syncthreads();

    {
        int w = tid >> 5, lane = tid & 31;
        #pragma unroll
        for (int rr = 0; rr < 8; rr++) {
            int row = w * 8 + rr;
            float a = ps[row * 64 + lane];
            float b = ps[row * 64 + lane + 32];
            float mx = fmaxf(a, b);
            #pragma unroll
            for (int off = 16; off > 0; off >>= 1)
                mx = fmaxf(mx, __shfl_xor_sync(0xffffffffu, mx, off));
            float ea = __expf(a - mx), eb = __expf(b - mx);
            float s = ea + eb;
            #pragma unroll
            for (int off = 16; off > 0; off >>= 1)
                s += __shfl_xor_sync(0xffffffffu, s, off);
            float inv = 1.0f / s;
            ps[row * 64 + lane]      = ea * inv;
            ps[row * 64 + lane + 32] = eb * inv;
        }
    }
    __syncthreads();

    float o[4][4] = {};
    #pragma unroll 4
    for (int m = 0; m < 64; m++) {
        float pv[4], vv[4];
        #pragma unroll
        for (int i = 0; i < 4; i++) pv[i] = ps[(ty * 4 + i) * 64 + m];
        #pragma unroll
        for (int j = 0; j < 4; j++) vv[j] = vs[m * 64 + tx * 4 + j];
        #pragma unroll
        for (int i = 0; i < 4; i++)
            #pragma unroll
            for (int j = 0; j < 4; j++)
                o[i][j] = fmaf(pv[i], vv[j], o[i][j]);
    }
    #pragma unroll
    for (int i = 0; i < 4; i++) {
        int n = ty * 4 + i;
        size_t ob = ((size_t)(win * 64 + n)) * CDIM + head * HD + tx * 4;
        __nv_bfloat16 h0, l0, h1, l1, h2, l2, h3, l3;
        split2(o[i][0], h0, l0); split2(o[i][1], h1, l1);
        split2(o[i][2], h2, l2); split2(o[i][3], h3, l3);
        *(__nv_bfloat162*)(outh + ob)     = __nv_bfloat162(h0, h1);
        *(__nv_bfloat162*)(outh + ob + 2) = __nv_bfloat162(h2, h3);
        *(__nv_bfloat162*)(outl + ob)     = __nv_bfloat162(l0, l1);
        *(__nv_bfloat162*)(outl + ob + 2) = __nv_bfloat162(l2, l3);
    }
}

// ---------------- launch ----------------
extern "C" void kernel_launch(void* const* d_in, const int* in_sizes, int n_in,
                              void* d_out, int out_size)
{
    const float* x      = (const float*)d_in[0];
    const float* ln1_g  = (const float*)d_in[1];
    const float* ln1_b  = (const float*)d_in[2];
    const float* qkv_w  = (const float*)d_in[3];
    const float* qkv_b  = (const float*)d_in[4];
    const float* proj_w = (const float*)d_in[5];
    const float* proj_b = (const float*)d_in[6];
    const float* ln2_g  = (const float*)d_in[7];
    const float* ln2_b  = (const float*)d_in[8];
    const float* ffn_w1 = (const float*)d_in[9];
    const float* ffn_b1 = (const float*)d_in[10];
    const float* ffn_w2 = (const float*)d_in[11];
    const float* ffn_b2 = (const float*)d_in[12];
    float* out = (float*)d_out;

    void* p;
    cudaGetSymbolAddress(&p, g_qkv);  float* qkvb = (float*)p;
    cudaGetSymbolAddress(&p, g_xo);   float* xo   = (float*)p;
    __nv_bfloat16 *y1h, *y1l, *ath, *atl, *y2h, *y2l, *hidh, *hidl;
    cudaGetSymbolAddress(&p, g_y1h);  y1h  = (__nv_bfloat16*)p;
    cudaGetSymbolAddress(&p, g_y1l);  y1l  = (__nv_bfloat16*)p;
    cudaGetSymbolAddress(&p, g_ath);  ath  = (__nv_bfloat16*)p;
    cudaGetSymbolAddress(&p, g_atl);  atl  = (__nv_bfloat16*)p;
    cudaGetSymbolAddress(&p, g_y2h);  y2h  = (__nv_bfloat16*)p;
    cudaGetSymbolAddress(&p, g_y2l);  y2l  = (__nv_bfloat16*)p;
    cudaGetSymbolAddress(&p, g_hidh); hidh = (__nv_bfloat16*)p;
    cudaGetSymbolAddress(&p, g_hidl); hidl = (__nv_bfloat16*)p;
    __nv_bfloat16 *wqh, *wql, *wph, *wpl, *w1h, *w1l, *w2h, *w2l;
    cudaGetSymbolAddress(&p, g_wqkv_hi); wqh = (__nv_bfloat16*)p;
    cudaGetSymbolAddress(&p, g_wqkv_lo); wql = (__nv_bfloat16*)p;
    cudaGetSymbolAddress(&p, g_wprj_hi); wph = (__nv_bfloat16*)p;
    cudaGetSymbolAddress(&p, g_wprj_lo); wpl = (__nv_bfloat16*)p;
    cudaGetSymbolAddress(&p, g_w1_hi);   w1h = (__nv_bfloat16*)p;
    cudaGetSymbolAddress(&p, g_w1_lo);   w1l = (__nv_bfloat16*)p;
    cudaGetSymbolAddress(&p, g_w2_hi);   w2h = (__nv_bfloat16*)p;
    cudaGetSymbolAddress(&p, g_w2_lo);   w2l = (__nv_bfloat16*)p;

    const int smem_attn = (2 * 64 * 65 + 64 * 64) * 4;
    cudaFuncSetAttribute(attn_kernel, cudaFuncAttributeMaxDynamicSharedMemorySize, smem_attn);
    cudaFuncSetAttribute(gemm_mma<EPI_NONE, 0>,    cudaFuncAttributeMaxDynamicSharedMemorySize, GT_SMEM);
    cudaFuncSetAttribute(gemm_mma<EPI_GELU, 1>,    cudaFuncAttributeMaxDynamicSharedMemorySize, GT_SMEM);
    cudaFuncSetAttribute(gemm_mma<EPI_RES_MAP, 0>, cudaFuncAttributeMaxDynamicSharedMemorySize, GT_SMEM);
    cudaFuncSetAttribute(gemm_mma<EPI_RES_NAT, 0>, cudaFuncAttributeMaxDynamicSharedMemorySize, GT_SMEM);

    // 0) weight transpose + bf16 split
    wsplit_kernel<<<dim3(QKVN / 32, CDIM / 32), 256>>>(qkv_w,  CDIM, QKVN, wqh, wql);
    wsplit_kernel<<<dim3(CDIM / 32, CDIM / 32), 256>>>(proj_w, CDIM, CDIM, wph, wpl);
    wsplit_kernel<<<dim3(HIDN / 32, CDIM / 32), 256>>>(ffn_w1, CDIM, HIDN, w1h, w1l);
    wsplit_kernel<<<dim3(CDIM / 32, HIDN / 32), 256>>>(ffn_w2, HIDN, CDIM, w2h, w2l);

    // 1) LN1 with shift+window gather -> split bf16
    ln_kernel<<<TOK, 256>>>(x, ln1_g, ln1_b, y1h, y1l, 1);

    // 2) QKV GEMM -> fp32 qkv
    gemm_mma<EPI_NONE, 0><<<dim3(QKVN / 128, TOK / 128), 256, GT_SMEM>>>(
        y1h, y1l, wqh, wql, qkv_b, nullptr, qkvb, nullptr, nullptr, TOK, QKVN, CDIM);

    // 3) attention -> split bf16
    attn_kernel<<<NWIN * NHEAD, 256, smem_attn>>>(qkvb, ath, atl);

    // 4) proj GEMM + residual(x) + scatter -> fp32 xo (natural)
    gemm_mma<EPI_RES_MAP, 0><<<dim3(CDIM / 128, TOK / 128), 256, GT_SMEM>>>(
        ath, atl, wph, wpl, proj_b, x, xo, nullptr, nullptr, TOK, CDIM, CDIM);

    // 5) LN2 -> split bf16
    ln_kernel<<<TOK, 256>>>(xo, ln2_g, ln2_b, y2h, y2l, 0);

    // 6) FFN1 + GELU -> split bf16 hidden
    gemm_mma<EPI_GELU, 1><<<dim3(HIDN / 128, TOK / 128), 256, GT_SMEM>>>(
        y2h, y2l, w1h, w1l, ffn_b1, nullptr, nullptr, hidh, hidl, TOK, HIDN, CDIM);

    // 7) FFN2 + residual(xo) -> out
    gemm_mma<EPI_RES_NAT, 0><<<dim3(CDIM / 128, TOK / 128), 256, GT_SMEM>>>(
        hidh, hidl, w2h, w2l, ffn_b2, xo, out, nullptr, nullptr, TOK, CDIM, HIDN);
}

// round 5
// speedup vs baseline: 2.4349x; 1.0010x over previous
#include <cuda_runtime.h>
#include <cuda_bf16.h>
#include <cstdint>
#include <math.h>

// ---------------- problem constants ----------------
#define TOK   65536          // 2*32*32*32 tokens
#define CDIM  512
#define QKVN  1536
#define HIDN  2048
#define NWIN  1024           // windows total (2 * 8^3)
#define NHEAD 8
#define HD    64

// ---------------- helpers ----------------
__device__ __forceinline__ uint32_t smem_to_u32(const void* p) {
    uint32_t a;
    asm("{ .reg .u64 t; cvta.to.shared.u64 t, %1; cvt.u32.u64 %0, t; }" : "=r"(a) : "l"(p));
    return a;
}

#define CP_ASYNC16(dst, src) \
    asm volatile("cp.async.cg.shared.global [%0], [%1], 16;" :: "r"(dst), "l"(src))
#define CP_COMMIT() asm volatile("cp.async.commit_group;" ::: "memory")
#define CP_WAIT0()  asm volatile("cp.async.wait_group 0;" ::: "memory")

#define LDSM_X4(r0, r1, r2, r3, addr) \
    asm volatile("ldmatrix.sync.aligned.m8n8.x4.shared.b16 {%0,%1,%2,%3}, [%4];" \
                 : "=r"(r0), "=r"(r1), "=r"(r2), "=r"(r3) : "r"(addr))

__device__ __forceinline__ void mma_bf16(float* c, const uint32_t* a, const uint32_t* b) {
    asm volatile(
        "mma.sync.aligned.m16n8k16.row.col.f32.bf16.bf16.f32 "
        "{%0,%1,%2,%3}, {%4,%5,%6,%7}, {%8,%9}, {%0,%1,%2,%3};"
        : "+f"(c[0]), "+f"(c[1]), "+f"(c[2]), "+f"(c[3])
        : "r"(a[0]), "r"(a[1]), "r"(a[2]), "r"(a[3]), "r"(b[0]), "r"(b[1]));
}

__device__ __forceinline__ void split2(float v, __nv_bfloat16& h, __nv_bfloat16& l) {
    h = __float2bfloat16(v);
    l = __float2bfloat16(v - __bfloat162float(h));
}

// ---------------- scratch (static device memory) ----------------
__device__ float g_qkv [(size_t)TOK * QKVN];                 // fp32 (attention input)
__device__ float g_xo  [(size_t)TOK * CDIM];                 // fp32 residual base
// pre-split bf16 activations (GEMM A-operands)
__device__ __nv_bfloat16 g_y1h [(size_t)TOK * CDIM];
__device__ __nv_bfloat16 g_y1l [(size_t)TOK * CDIM];
__device__ __nv_bfloat16 g_ath [(size_t)TOK * CDIM];
__device__ __nv_bfloat16 g_atl [(size_t)TOK * CDIM];
__device__ __nv_bfloat16 g_y2h [(size_t)TOK * CDIM];
__device__ __nv_bfloat16 g_y2l [(size_t)TOK * CDIM];
__device__ __nv_bfloat16 g_hidh[(size_t)TOK * HIDN];
__device__ __nv_bfloat16 g_hidl[(size_t)TOK * HIDN];
// weight transposed+split buffers: [N, K] bf16 hi/lo
__device__ __nv_bfloat16 g_wqkv_hi[(size_t)QKVN * CDIM];
__device__ __nv_bfloat16 g_wqkv_lo[(size_t)QKVN * CDIM];
__device__ __nv_bfloat16 g_wprj_hi[(size_t)CDIM * CDIM];
__device__ __nv_bfloat16 g_wprj_lo[(size_t)CDIM * CDIM];
__device__ __nv_bfloat16 g_w1_hi  [(size_t)HIDN * CDIM];
__device__ __nv_bfloat16 g_w1_lo  [(size_t)HIDN * CDIM];
__device__ __nv_bfloat16 g_w2_hi  [(size_t)CDIM * HIDN];
__device__ __nv_bfloat16 g_w2_lo  [(size_t)CDIM * HIDN];

// window-ordered row r -> natural token index t
__device__ __forceinline__ int wr2t(int r) {
    int n   = r & 63;
    int win = r >> 6;
    int ww  = win & 7, wh = (win >> 3) & 7, wd = (win >> 6) & 7, b = win >> 9;
    int zw  = n & 3,  zh = (n >> 2) & 3,  zd = n >> 4;
    int d = (wd * 4 + zd + 2) & 31;
    int h = (wh * 4 + zh + 2) & 31;
    int w = (ww * 4 + zw + 2) & 31;
    return ((b * 32 + d) * 32 + h) * 32 + w;
}

__device__ __forceinline__ float gelu_exact(float v) {
    return 0.5f * v * (1.0f + erff(v * 0.70710678118654752f));
}

// ---------------- weight transpose + bf16 split ----------------
__global__ __launch_bounds__(256)
void wsplit_kernel(const float* __restrict__ W, int K, int N,
                   __nv_bfloat16* __restrict__ Whi, __nv_bfloat16* __restrict__ Wlo)
{
    __shared__ float tile[32][33];
    int n0 = blockIdx.x * 32, k0 = blockIdx.y * 32;
    int tx = threadIdx.x & 31, ty = threadIdx.x >> 5;   // 32 x 8
    #pragma unroll
    for (int r = 0; r < 4; r++) {
        int kk = ty + r * 8;
        tile[kk][tx] = W[(size_t)(k0 + kk) * N + n0 + tx];
    }
    __syncthreads();
    #pragma unroll
    for (int r = 0; r < 4; r++) {
        int nn = ty + r * 8;
        float v = tile[tx][nn];
        __nv_bfloat16 h, l;
        split2(v, h, l);
        size_t o = (size_t)(n0 + nn) * K + k0 + tx;
        Whi[o] = h;
        Wlo[o] = l;
    }
}

// ---------------- LayerNorm -> split bf16 hi/lo ----------------
__global__ __launch_bounds__(256)
void ln_kernel(const float* __restrict__ X, const float* __restrict__ gam,
               const float* __restrict__ bet,
               __nv_bfloat16* __restrict__ Yh, __nv_bfloat16* __restrict__ Yl,
               int gather)
{
    __shared__ float red[16];
    int r   = blockIdx.x;
    int src = gather ? wr2t(r) : r;
    const float* xr = X + (size_t)src * CDIM;
    int t = threadIdx.x;
    float v0 = xr[t], v1 = xr[t + 256];
    float s = v0 + v1;
    float q = v0 * v0 + v1 * v1;
    #pragma unroll
    for (int off = 16; off > 0; off >>= 1) {
        s += __shfl_xor_sync(0xffffffffu, s, off);
        q += __shfl_xor_sync(0xffffffffu, q, off);
    }
    int w = t >> 5, lane = t & 31;
    if (lane == 0) { red[w] = s; red[8 + w] = q; }
    __syncthreads();
    if (w == 0) {
        float s2 = (lane < 8) ? red[lane] : 0.f;
        float q2 = (lane < 8) ? red[8 + lane] : 0.f;
        #pragma unroll
        for (int off = 4; off > 0; off >>= 1) {
            s2 += __shfl_xor_sync(0xffffffffu, s2, off);
            q2 += __shfl_xor_sync(0xffffffffu, q2, off);
        }
        if (lane == 0) { red[0] = s2; red[1] = q2; }
    }
    __syncthreads();
    float mean = red[0] * (1.0f / CDIM);
    float var  = red[1] * (1.0f / CDIM) - mean * mean;
    float rstd = rsqrtf(var + 1e-5f);
    size_t rb = (size_t)r * CDIM;
    float y0 = (v0 - mean) * rstd * gam[t]       + bet[t];
    float y1 = (v1 - mean) * rstd * gam[t + 256] + bet[t + 256];
    __nv_bfloat16 h, l;
    split2(y0, h, l); Yh[rb + t] = h;       Yl[rb + t] = l;
    split2(y1, h, l); Yh[rb + t + 256] = h; Yl[rb + t + 256] = l;
}

// ---------------- tensor-core GEMM via mma.sync (bf16 3-term split) -------
// C[M,N] = A[M,K] @ B[K,N] + bias;  A pre-split [M,K] hi/lo, B pre-split [N,K] hi/lo.
// CTA 128x128, 8 warps in 2(M)x4(N), warp tile 64x32, BK=32, double buffer.
// Mainloop is term-sequential (hi*hi, lo*hi, hi*lo) to keep fragment liveness
// low enough for 2 CTAs/SM at <=128 regs (no spills).
#define EPI_NONE    0
#define EPI_GELU    1
#define EPI_RES_MAP 2
#define EPI_RES_NAT 3

#define ROWPITCH 80
#define REG_A    0
#define REG_AL   10240
#define REG_B    20480
#define REG_BL   30720
#define BUFSZ    40960
#define GT_SMEM  (2 * BUFSZ)

template<int EPI, int OUTSPLIT>
__global__ __launch_bounds__(256, 2)
void gemm_mma(const __nv_bfloat16* __restrict__ Ahi, const __nv_bfloat16* __restrict__ Alo,
              const __nv_bfloat16* __restrict__ Bhi, const __nv_bfloat16* __restrict__ Blo,
              const float* __restrict__ bias, const float* __restrict__ R,
              float* __restrict__ C, __nv_bfloat16* __restrict__ Chi,
              __nv_bfloat16* __restrict__ Clo, int M, int N, int K)
{
    extern __shared__ char sm[];
    const uint32_t smb = smem_to_u32(sm);
    const int tid  = threadIdx.x;
    const int wid  = tid >> 5, lane = tid & 31;
    const int wm   = wid & 1,  wn   = wid >> 1;
    const int row0 = blockIdx.y * 128, col0 = blockIdx.x * 128;

    const int s0row = tid >> 2, s0k8 = (tid & 3) * 8;   // seg tid
    const int s1row = s0row + 64;                        // seg tid + 256
    const uint32_t so0 = (uint32_t)(s0row * ROWPITCH + s0k8 * 2);
    const uint32_t so1 = (uint32_t)(s1row * ROWPITCH + s0k8 * 2);

    const int g = lane >> 3, r = lane & 7;
    const uint32_t aoff = (uint32_t)((wm * 64 + (g & 1) * 8 + r) * ROWPITCH + (g >> 1) * 16);
    const uint32_t boff = (uint32_t)(((g >> 1) * 8 + r + wn * 32) * ROWPITCH + (g & 1) * 16);

    float acc[4][4][4];
    #pragma unroll
    for (int i = 0; i < 4; i++)
        #pragma unroll
        for (int j = 0; j < 4; j++)
            #pragma unroll
            for (int e = 0; e < 4; e++) acc[i][j][e] = 0.f;

    const int NC = K >> 5;

    auto load_chunk = [&](int kc, int buf) {
        const uint32_t bb = smb + buf * BUFSZ;
        size_t ga0 = (size_t)(row0 + s0row) * K + kc + s0k8;
        size_t ga1 = (size_t)(row0 + s1row) * K + kc + s0k8;
        CP_ASYNC16(bb + REG_A  + so0, Ahi + ga0);
        CP_ASYNC16(bb + REG_AL + so0, Alo + ga0);
        CP_ASYNC16(bb + REG_A  + so1, Ahi + ga1);
        CP_ASYNC16(bb + REG_AL + so1, Alo + ga1);
        size_t gb0 = (size_t)(col0 + s0row) * K + kc + s0k8;
        size_t gb1 = (size_t)(col0 + s1row) * K + kc + s0k8;
        CP_ASYNC16(bb + REG_B  + so0, Bhi + gb0);
        CP_ASYNC16(bb + REG_BL + so0, Blo + gb0);
        CP_ASYNC16(bb + REG_B  + so1, Bhi + gb1);
        CP_ASYNC16(bb + REG_BL + so1, Blo + gb1);
        CP_COMMIT();
    };

    load_chunk(0, 0);
    CP_WAIT0();
    __syncthreads();

    for (int c = 0; c < NC; c++) {
        const int buf = c & 1;
        const uint32_t ab = smb + buf * BUFSZ;

        if (c + 1 < NC) load_chunk((c + 1) * 32, buf ^ 1);

        #pragma unroll
        for (int s = 0; s < 2; s++) {
            // --- term 1: hi * hi ---
            uint32_t ah[4][4], bh[4][2];
            #pragma unroll
            for (int mi = 0; mi < 4; mi++) {
                uint32_t addr = ab + aoff + mi * (16 * ROWPITCH) + s * 32;
                LDSM_X4(ah[mi][0], ah[mi][1], ah[mi][2], ah[mi][3], addr + REG_A);
            }
            #pragma unroll
            for (int nj = 0; nj < 2; nj++) {
                uint32_t addr = ab + boff + nj * (16 * ROWPITCH) + s * 32;
                LDSM_X4(bh[nj*2][0], bh[nj*2][1], bh[nj*2+1][0], bh[nj*2+1][1], addr + REG_B);
            }
            #pragma unroll
            for (int mi = 0; mi < 4; mi++)
                #pragma unroll
                for (int ni = 0; ni < 4; ni++)
                    mma_bf16(acc[mi][ni], ah[mi], bh[ni]);

            // --- term 2: lo * hi (al dies after this block) ---
            {
                uint32_t al[4][4];
                #pragma unroll
                for (int mi = 0; mi < 4; mi++) {
                    uint32_t addr = ab + aoff + mi * (16 * ROWPITCH) + s * 32;
                    LDSM_X4(al[mi][0], al[mi][1], al[mi][2], al[mi][3], addr + REG_AL);
                }
                #pragma unroll
                for (int mi = 0; mi < 4; mi++)
                    #pragma unroll
                    for (int ni = 0; ni < 4; ni++)
                        mma_bf16(acc[mi][ni], al[mi], bh[ni]);
            }

            // --- term 3: hi * lo ---
            {
                uint32_t bl[4][2];
                #pragma unroll
                for (int nj = 0; nj < 2; nj++) {
                    uint32_t addr = ab + boff + nj * (16 * ROWPITCH) + s * 32;
                    LDSM_X4(bl[nj*2][0], bl[nj*2][1], bl[nj*2+1][0], bl[nj*2+1][1], addr + REG_BL);
                }
                #pragma unroll
                for (int mi = 0; mi < 4; mi++)
                    #pragma unroll
                    for (int ni = 0; ni < 4; ni++)
                        mma_bf16(acc[mi][ni], ah[mi], bl[ni]);
            }
        }

        if (c + 1 < NC) CP_WAIT0();
        __syncthreads();
    }

    // ---- epilogue ----
    const int qrow = lane >> 2;
    const int qcol = (lane & 3) * 2;
    #pragma unroll
    for (int mi = 0; mi < 4; mi++) {
        int gr0 = row0 + wm * 64 + mi * 16 + qrow;
        int gr1 = gr0 + 8;
        int or0 = (EPI == EPI_RES_MAP) ? wr2t(gr0) : gr0;
        int or1 = (EPI == EPI_RES_MAP) ? wr2t(gr1) : gr1;
        #pragma unroll
        for (int ni = 0; ni < 4; ni++) {
            int col = col0 + wn * 32 + ni * 8 + qcol;
            float b0 = bias[col], b1 = bias[col + 1];
            float v00 = acc[mi][ni][0] + b0, v01 = acc[mi][ni][1] + b1;
            float v10 = acc[mi][ni][2] + b0, v11 = acc[mi][ni][3] + b1;
            if (EPI == EPI_GELU) {
                v00 = gelu_exact(v00); v01 = gelu_exact(v01);
                v10 = gelu_exact(v10); v11 = gelu_exact(v11);
            }
            if (EPI == EPI_RES_MAP || EPI == EPI_RES_NAT) {
                float2 r0v = *(const float2*)(R + (size_t)or0 * N + col);
                float2 r1v = *(const float2*)(R + (size_t)or1 * N + col);
                v00 += r0v.x; v01 += r0v.y; v10 += r1v.x; v11 += r1v.y;
            }
            if (OUTSPLIT) {
                __nv_bfloat16 h0, l0, h1, l1;
                split2(v00, h0, l0); split2(v01, h1, l1);
                *(__nv_bfloat162*)(Chi + (size_t)or0 * N + col) = __nv_bfloat162(h0, h1);
                *(__nv_bfloat162*)(Clo + (size_t)or0 * N + col) = __nv_bfloat162(l0, l1);
                split2(v10, h0, l0); split2(v11, h1, l1);
                *(__nv_bfloat162*)(Chi + (size_t)or1 * N + col) = __nv_bfloat162(h0, h1);
                *(__nv_bfloat162*)(Clo + (size_t)or1 * N + col) = __nv_bfloat162(l0, l1);
            } else {
                *(float2*)(C + (size_t)or0 * N + col) = make_float2(v00, v01);
                *(float2*)(C + (size_t)or1 * N + col) = make_float2(v10, v11);
            }
        }
    }
}

// ---------------- windowed attention: one block per (window, head) -------
__global__ __launch_bounds__(256)
void attn_kernel(const float* __restrict__ qkv,
                 __nv_bfloat16* __restrict__ outh, __nv_bfloat16* __restrict__ outl)
{
    extern __shared__ float smf[];
    float* qts = smf;
    float* kts = smf + 64 * 65;
    float* vs  = smf + 2 * 64 * 65;
    float* ps  = smf;

    const int tid  = threadIdx.x;
    const int win  = blockIdx.x >> 3;
    const int head = blockIdx.x & 7;
    const size_t base0 = (size_t)win * 64 * QKVN + head * HD;

    for (int e = tid; e < 4096; e += 256) {
        int n = e >> 6, dd = e & 63;
        size_t base = base0 + (size_t)n * QKVN + dd;
        qts[dd * 65 + n] = qkv[base];
        kts[dd * 65 + n] = qkv[base + 512];
        vs[n * 64 + dd]  = qkv[base + 1024];
    }
    __syncthreads();

    const int tx = tid & 15, ty = tid >> 4;
    float acc[4][4] = {};
    #pragma unroll 4
    for (int dd = 0; dd < 64; dd++) {
        float qa[4], kb[4];
        #pragma unroll
        for (int i = 0; i < 4; i++) qa[i] = qts[dd * 65 + ty * 4 + i];
        #pragma unroll
        for (int j = 0; j < 4; j++) kb[j] = kts[dd * 65 + tx * 4 + j];
        #pragma unroll
        for (int i = 0; i < 4; i++)
            #pragma unroll
            for (int j = 0; j < 4; j++)
                acc[i][j] = fmaf(qa[i], kb[j], acc[i][j]);
    }
    __syncthreads();
    #pragma unroll
    for (int i = 0; i < 4; i++)
        #pragma unroll
        for (int j = 0; j < 4; j++)
            ps[(ty * 4 + i) * 64 + tx * 4 + j] = acc[i][j] * 0.125f;
    __syncthreads();

    {
        int w = tid >> 5, lane = tid & 31;
        #pragma unroll
        for (int rr = 0; rr < 8; rr++) {
            int row = w * 8 + rr;
            float a = ps[row * 64 + lane];
            float b = ps[row * 64 + lane + 32];
            float mx = fmaxf(a, b);
            #pragma unroll
            for (int off = 16; off > 0; off >>= 1)
                mx = fmaxf(mx, __shfl_xor_sync(0xffffffffu, mx, off));
            float ea = __expf(a - mx), eb = __expf(b - mx);
            float s = ea + eb;
            #pragma unroll
            for (int off = 16; off > 0; off >>= 1)
                s += __shfl_xor_sync(0xffffffffu, s, off);
            float inv = 1.0f / s;
            ps[row * 64 + lane]      = ea * inv;
            ps[row * 64 + lane + 32] = eb * inv;
        }
    }
    __syncthreads();

    float o[4][4] = {};
    #pragma unroll 4
    for (int m = 0; m < 64; m++) {
        float pv[4], vv[4];
        #pragma unroll
        for (int i = 0; i < 4; i++) pv[i] = ps[(ty * 4 + i) * 64 + m];
        #pragma unroll
        for (int j = 0; j < 4; j++) vv[j] = vs[m * 64 + tx * 4 + j];
        #pragma unroll
        for (int i = 0; i < 4; i++)
            #pragma unroll
            for (int j = 0; j < 4; j++)
                o[i][j] = fmaf(pv[i], vv[j], o[i][j]);
    }
    #pragma unroll
    for (int i = 0; i < 4; i++) {
        int n = ty * 4 + i;
        size_t ob = ((size_t)(win * 64 + n)) * CDIM + head * HD + tx * 4;
        __nv_bfloat16 h0, l0, h1, l1, h2, l2, h3, l3;
        split2(o[i][0], h0, l0); split2(o[i][1], h1, l1);
        split2(o[i][2], h2, l2); split2(o[i][3], h3, l3);
        *(__nv_bfloat162*)(outh + ob)     = __nv_bfloat162(h0, h1);
        *(__nv_bfloat162*)(outh + ob + 2) = __nv_bfloat162(h2, h3);
        *(__nv_bfloat162*)(outl + ob)     = __nv_bfloat162(l0, l1);
        *(__nv_bfloat162*)(outl + ob + 2) = __nv_bfloat162(l2, l3);
    }
}

// ---------------- launch ----------------
extern "C" void kernel_launch(void* const* d_in, const int* in_sizes, int n_in,
                              void* d_out, int out_size)
{
    const float* x      = (const float*)d_in[0];
    const float* ln1_g  = (const float*)d_in[1];
    const float* ln1_b  = (const float*)d_in[2];
    const float* qkv_w  = (const float*)d_in[3];
    const float* qkv_b  = (const float*)d_in[4];
    const float* proj_w = (const float*)d_in[5];
    const float* proj_b = (const float*)d_in[6];
    const float* ln2_g  = (const float*)d_in[7];
    const float* ln2_b  = (const float*)d_in[8];
    const float* ffn_w1 = (const float*)d_in[9];
    const float* ffn_b1 = (const float*)d_in[10];
    const float* ffn_w2 = (const float*)d_in[11];
    const float* ffn_b2 = (const float*)d_in[12];
    float* out = (float*)d_out;

    void* p;
    cudaGetSymbolAddress(&p, g_qkv);  float* qkvb = (float*)p;
    cudaGetSymbolAddress(&p, g_xo);   float* xo   = (float*)p;
    __nv_bfloat16 *y1h, *y1l, *ath, *atl, *y2h, *y2l, *hidh, *hidl;
    cudaGetSymbolAddress(&p, g_y1h);  y1h  = (__nv_bfloat16*)p;
    cudaGetSymbolAddress(&p, g_y1l);  y1l  = (__nv_bfloat16*)p;
    cudaGetSymbolAddress(&p, g_ath);  ath  = (__nv_bfloat16*)p;
    cudaGetSymbolAddress(&p, g_atl);  atl  = (__nv_bfloat16*)p;
    cudaGetSymbolAddress(&p, g_y2h);  y2h  = (__nv_bfloat16*)p;
    cudaGetSymbolAddress(&p, g_y2l);  y2l  = (__nv_bfloat16*)p;
    cudaGetSymbolAddress(&p, g_hidh); hidh = (__nv_bfloat16*)p;
    cudaGetSymbolAddress(&p, g_hidl); hidl = (__nv_bfloat16*)p;
    __nv_bfloat16 *wqh, *wql, *wph, *wpl, *w1h, *w1l, *w2h, *w2l;
    cudaGetSymbolAddress(&p, g_wqkv_hi); wqh = (__nv_bfloat16*)p;
    cudaGetSymbolAddress(&p, g_wqkv_lo); wql = (__nv_bfloat16*)p;
    cudaGetSymbolAddress(&p, g_wprj_hi); wph = (__nv_bfloat16*)p;
    cudaGetSymbolAddress(&p, g_wprj_lo); wpl = (__nv_bfloat16*)p;
    cudaGetSymbolAddress(&p, g_w1_hi);   w1h = (__nv_bfloat16*)p;
    cudaGetSymbolAddress(&p, g_w1_lo);   w1l = (__nv_bfloat16*)p;
    cudaGetSymbolAddress(&p, g_w2_hi);   w2h = (__nv_bfloat16*)p;
    cudaGetSymbolAddress(&p, g_w2_lo);   w2l = (__nv_bfloat16*)p;

    const int smem_attn = (2 * 64 * 65 + 64 * 64) * 4;
    cudaFuncSetAttribute(attn_kernel, cudaFuncAttributeMaxDynamicSharedMemorySize, smem_attn);
    cudaFuncSetAttribute(gemm_mma<EPI_NONE, 0>,    cudaFuncAttributeMaxDynamicSharedMemorySize, GT_SMEM);
    cudaFuncSetAttribute(gemm_mma<EPI_GELU, 1>,    cudaFuncAttributeMaxDynamicSharedMemorySize, GT_SMEM);
    cudaFuncSetAttribute(gemm_mma<EPI_RES_MAP, 0>, cudaFuncAttributeMaxDynamicSharedMemorySize, GT_SMEM);
    cudaFuncSetAttribute(gemm_mma<EPI_RES_NAT, 0>, cudaFuncAttributeMaxDynamicSharedMemorySize, GT_SMEM);

    // 0) weight transpose + bf16 split
    wsplit_kernel<<<dim3(QKVN / 32, CDIM / 32), 256>>>(qkv_w,  CDIM, QKVN, wqh, wql);
    wsplit_kernel<<<dim3(CDIM / 32, CDIM / 32), 256>>>(proj_w, CDIM, CDIM, wph, wpl);
    wsplit_kernel<<<dim3(HIDN / 32, CDIM / 32), 256>>>(ffn_w1, CDIM, HIDN, w1h, w1l);
    wsplit_kernel<<<dim3(CDIM / 32, HIDN / 32), 256>>>(ffn_w2, HIDN, CDIM, w2h, w2l);

    // 1) LN1 with shift+window gather -> split bf16
    ln_kernel<<<TOK, 256>>>(x, ln1_g, ln1_b, y1h, y1l, 1);

    // 2) QKV GEMM -> fp32 qkv
    gemm_mma<EPI_NONE, 0><<<dim3(QKVN / 128, TOK / 128), 256, GT_SMEM>>>(
        y1h, y1l, wqh, wql, qkv_b, nullptr, qkvb, nullptr, nullptr, TOK, QKVN, CDIM);

    // 3) attention -> split bf16
    attn_kernel<<<NWIN * NHEAD, 256, smem_attn>>>(qkvb, ath, atl);

    // 4) proj GEMM + residual(x) + scatter -> fp32 xo (natural)
    gemm_mma<EPI_RES_MAP, 0><<<dim3(CDIM / 128, TOK / 128), 256, GT_SMEM>>>(
        ath, atl, wph, wpl, proj_b, x, xo, nullptr, nullptr, TOK, CDIM, CDIM);

    // 5) LN2 -> split bf16
    ln_kernel<<<TOK, 256>>>(xo, ln2_g, ln2_b, y2h, y2l, 0);

    // 6) FFN1 + GELU -> split bf16 hidden
    gemm_mma<EPI_GELU, 1><<<dim3(HIDN / 128, TOK / 128), 256, GT_SMEM>>>(
        y2h, y2l, w1h, w1l, ffn_b1, nullptr, nullptr, hidh, hidl, TOK, HIDN, CDIM);

    // 7) FFN2 + residual(xo) -> out
    gemm_mma<EPI_RES_NAT, 0><<<dim3(CDIM / 128, TOK / 128), 256, GT_SMEM>>>(
        hidh, hidl, w2h, w2l, ffn_b2, xo, out, nullptr, nullptr, TOK, CDIM, HIDN);
}

// round 6
// speedup vs baseline: 3.3982x; 1.3956x over previous
#include <cuda_runtime.h>
#include <cuda_fp16.h>
#include <cstdint>
#include <math.h>

// ---------------- problem constants ----------------
#define TOK   65536          // 2*32*32*32 tokens
#define CDIM  512
#define QKVN  1536
#define HIDN  2048
#define NWIN  1024           // windows total (2 * 8^3)
#define NHEAD 8
#define HD    64

// ---------------- helpers ----------------
__device__ __forceinline__ uint32_t smem_to_u32(const void* p) {
    uint32_t a;
    asm("{ .reg .u64 t; cvta.to.shared.u64 t, %1; cvt.u32.u64 %0, t; }" : "=r"(a) : "l"(p));
    return a;
}

#define CP_ASYNC16(dst, src) \
    asm volatile("cp.async.cg.shared.global [%0], [%1], 16;" :: "r"(dst), "l"(src))
#define CP_COMMIT() asm volatile("cp.async.commit_group;" ::: "memory")
#define CP_WAIT0()  asm volatile("cp.async.wait_group 0;" ::: "memory")

#define LDSM_X4(r0, r1, r2, r3, addr) \
    asm volatile("ldmatrix.sync.aligned.m8n8.x4.shared.b16 {%0,%1,%2,%3}, [%4];" \
                 : "=r"(r0), "=r"(r1), "=r"(r2), "=r"(r3) : "r"(addr))

__device__ __forceinline__ void mma_f16(float* c, const uint32_t* a, const uint32_t* b) {
    asm volatile(
        "mma.sync.aligned.m16n8k16.row.col.f32.f16.f16.f32 "
        "{%0,%1,%2,%3}, {%4,%5,%6,%7}, {%8,%9}, {%0,%1,%2,%3};"
        : "+f"(c[0]), "+f"(c[1]), "+f"(c[2]), "+f"(c[3])
        : "r"(a[0]), "r"(a[1]), "r"(a[2]), "r"(a[3]), "r"(b[0]), "r"(b[1]));
}

__device__ __forceinline__ void split2h(float v, __half& h, __half& l) {
    h = __float2half_rn(v);
    l = __float2half_rn(v - __half2float(h));
}

// ---------------- scratch (static device memory) ----------------
__device__ float g_qkv [(size_t)TOK * QKVN];                 // fp32 (attention input)
__device__ float g_xo  [(size_t)TOK * CDIM];                 // fp32 residual base
// fp16 activations (GEMM A-operands, single precision copy)
__device__ __half g_y1 [(size_t)TOK * CDIM];
__device__ __half g_at [(size_t)TOK * CDIM];
__device__ __half g_y2 [(size_t)TOK * CDIM];
__device__ __half g_hid[(size_t)TOK * HIDN];
// weight transposed+split buffers: [N, K] fp16 hi/lo
__device__ __half g_wqkv_hi[(size_t)QKVN * CDIM];
__device__ __half g_wqkv_lo[(size_t)QKVN * CDIM];
__device__ __half g_wprj_hi[(size_t)CDIM * CDIM];
__device__ __half g_wprj_lo[(size_t)CDIM * CDIM];
__device__ __half g_w1_hi  [(size_t)HIDN * CDIM];
__device__ __half g_w1_lo  [(size_t)HIDN * CDIM];
__device__ __half g_w2_hi  [(size_t)CDIM * HIDN];
__device__ __half g_w2_lo  [(size_t)CDIM * HIDN];

// window-ordered row r -> natural token index t
__device__ __forceinline__ int wr2t(int r) {
    int n   = r & 63;
    int win = r >> 6;
    int ww  = win & 7, wh = (win >> 3) & 7, wd = (win >> 6) & 7, b = win >> 9;
    int zw  = n & 3,  zh = (n >> 2) & 3,  zd = n >> 4;
    int d = (wd * 4 + zd + 2) & 31;
    int h = (wh * 4 + zh + 2) & 31;
    int w = (ww * 4 + zw + 2) & 31;
    return ((b * 32 + d) * 32 + h) * 32 + w;
}

__device__ __forceinline__ float gelu_exact(float v) {
    return 0.5f * v * (1.0f + erff(v * 0.70710678118654752f));
}

// ---------------- weight transpose + fp16 split ----------------
__global__ __launch_bounds__(256)
void wsplit_kernel(const float* __restrict__ W, int K, int N,
                   __half* __restrict__ Whi, __half* __restrict__ Wlo)
{
    __shared__ float tile[32][33];
    int n0 = blockIdx.x * 32, k0 = blockIdx.y * 32;
    int tx = threadIdx.x & 31, ty = threadIdx.x >> 5;   // 32 x 8
    #pragma unroll
    for (int r = 0; r < 4; r++) {
        int kk = ty + r * 8;
        tile[kk][tx] = W[(size_t)(k0 + kk) * N + n0 + tx];
    }
    __syncthreads();
    #pragma unroll
    for (int r = 0; r < 4; r++) {
        int nn = ty + r * 8;
        float v = tile[tx][nn];
        __half h, l;
        split2h(v, h, l);
        size_t o = (size_t)(n0 + nn) * K + k0 + tx;
        Whi[o] = h;
        Wlo[o] = l;
    }
}

// ---------------- LayerNorm -> fp16 ----------------
__global__ __launch_bounds__(256)
void ln_kernel(const float* __restrict__ X, const float* __restrict__ gam,
               const float* __restrict__ bet, __half* __restrict__ Y, int gather)
{
    __shared__ float red[16];
    int r   = blockIdx.x;
    int src = gather ? wr2t(r) : r;
    const float* xr = X + (size_t)src * CDIM;
    int t = threadIdx.x;
    float v0 = xr[t], v1 = xr[t + 256];
    float s = v0 + v1;
    float q = v0 * v0 + v1 * v1;
    #pragma unroll
    for (int off = 16; off > 0; off >>= 1) {
        s += __shfl_xor_sync(0xffffffffu, s, off);
        q += __shfl_xor_sync(0xffffffffu, q, off);
    }
    int w = t >> 5, lane = t & 31;
    if (lane == 0) { red[w] = s; red[8 + w] = q; }
    __syncthreads();
    if (w == 0) {
        float s2 = (lane < 8) ? red[lane] : 0.f;
        float q2 = (lane < 8) ? red[8 + lane] : 0.f;
        #pragma unroll
        for (int off = 4; off > 0; off >>= 1) {
            s2 += __shfl_xor_sync(0xffffffffu, s2, off);
            q2 += __shfl_xor_sync(0xffffffffu, q2, off);
        }
        if (lane == 0) { red[0] = s2; red[1] = q2; }
    }
    __syncthreads();
    float mean = red[0] * (1.0f / CDIM);
    float var  = red[1] * (1.0f / CDIM) - mean * mean;
    float rstd = rsqrtf(var + 1e-5f);
    size_t rb = (size_t)r * CDIM;
    float y0 = (v0 - mean) * rstd * gam[t]       + bet[t];
    float y1 = (v1 - mean) * rstd * gam[t + 256] + bet[t + 256];
    Y[rb + t]       = __float2half_rn(y0);
    Y[rb + t + 256] = __float2half_rn(y1);
}

// ---------------- tensor-core GEMM via mma.sync (fp16, 2-term weight split) -
// C[M,N] = A[M,K] @ B[K,N] + bias;  A fp16 [M,K], B pre-split [N,K] fp16 hi/lo.
// CTA 128x128, 8 warps in 2(M)x4(N), warp tile 64x32, BK=32, double buffer.
#define EPI_NONE    0
#define EPI_GELU    1
#define EPI_RES_MAP 2
#define EPI_RES_NAT 3

#define ROWPITCH 80
#define REG_A    0
#define REG_B    10240
#define REG_BL   20480
#define BUFSZ    30720
#define GT_SMEM  (2 * BUFSZ)

template<int EPI, int OUTH>
__global__ __launch_bounds__(256, 2)
void gemm_mma(const __half* __restrict__ A,
              const __half* __restrict__ Bhi, const __half* __restrict__ Blo,
              const float* __restrict__ bias, const float* __restrict__ R,
              float* __restrict__ C, __half* __restrict__ Ch, int M, int N, int K)
{
    extern __shared__ char sm[];
    const uint32_t smb = smem_to_u32(sm);
    const int tid  = threadIdx.x;
    const int wid  = tid >> 5, lane = tid & 31;
    const int wm   = wid & 1,  wn   = wid >> 1;
    const int row0 = blockIdx.y * 128, col0 = blockIdx.x * 128;

    const int s0row = tid >> 2, s0k8 = (tid & 3) * 8;   // seg tid
    const int s1row = s0row + 64;                        // seg tid + 256
    const uint32_t so0 = (uint32_t)(s0row * ROWPITCH + s0k8 * 2);
    const uint32_t so1 = (uint32_t)(s1row * ROWPITCH + s0k8 * 2);

    const int g = lane >> 3, r = lane & 7;
    const uint32_t aoff = (uint32_t)((wm * 64 + (g & 1) * 8 + r) * ROWPITCH + (g >> 1) * 16);
    const uint32_t boff = (uint32_t)(((g >> 1) * 8 + r + wn * 32) * ROWPITCH + (g & 1) * 16);

    float acc[4][4][4];
    #pragma unroll
    for (int i = 0; i < 4; i++)
        #pragma unroll
        for (int j = 0; j < 4; j++)
            #pragma unroll
            for (int e = 0; e < 4; e++) acc[i][j][e] = 0.f;

    const int NC = K >> 5;

    auto load_chunk = [&](int kc, int buf) {
        const uint32_t bb = smb + buf * BUFSZ;
        size_t ga0 = (size_t)(row0 + s0row) * K + kc + s0k8;
        size_t ga1 = (size_t)(row0 + s1row) * K + kc + s0k8;
        CP_ASYNC16(bb + REG_A + so0, A + ga0);
        CP_ASYNC16(bb + REG_A + so1, A + ga1);
        size_t gb0 = (size_t)(col0 + s0row) * K + kc + s0k8;
        size_t gb1 = (size_t)(col0 + s1row) * K + kc + s0k8;
        CP_ASYNC16(bb + REG_B  + so0, Bhi + gb0);
        CP_ASYNC16(bb + REG_BL + so0, Blo + gb0);
        CP_ASYNC16(bb + REG_B  + so1, Bhi + gb1);
        CP_ASYNC16(bb + REG_BL + so1, Blo + gb1);
        CP_COMMIT();
    };

    load_chunk(0, 0);
    CP_WAIT0();
    __syncthreads();

    for (int c = 0; c < NC; c++) {
        const int buf = c & 1;
        const uint32_t ab = smb + buf * BUFSZ;

        if (c + 1 < NC) load_chunk((c + 1) * 32, buf ^ 1);

        #pragma unroll
        for (int s = 0; s < 2; s++) {
            uint32_t ah[4][4], bh[4][2];
            #pragma unroll
            for (int mi = 0; mi < 4; mi++) {
                uint32_t addr = ab + aoff + mi * (16 * ROWPITCH) + s * 32;
                LDSM_X4(ah[mi][0], ah[mi][1], ah[mi][2], ah[mi][3], addr + REG_A);
            }
            // term 1: a * bh
            #pragma unroll
            for (int nj = 0; nj < 2; nj++) {
                uint32_t addr = ab + boff + nj * (16 * ROWPITCH) + s * 32;
                LDSM_X4(bh[nj*2][0], bh[nj*2][1], bh[nj*2+1][0], bh[nj*2+1][1], addr + REG_B);
            }
            #pragma unroll
            for (int mi = 0; mi < 4; mi++)
                #pragma unroll
                for (int ni = 0; ni < 4; ni++)
                    mma_f16(acc[mi][ni], ah[mi], bh[ni]);
            // term 2: a * bl  (A fragments reused)
            #pragma unroll
            for (int nj = 0; nj < 2; nj++) {
                uint32_t addr = ab + boff + nj * (16 * ROWPITCH) + s * 32;
                LDSM_X4(bh[nj*2][0], bh[nj*2][1], bh[nj*2+1][0], bh[nj*2+1][1], addr + REG_BL);
            }
            #pragma unroll
            for (int mi = 0; mi < 4; mi++)
                #pragma unroll
                for (int ni = 0; ni < 4; ni++)
                    mma_f16(acc[mi][ni], ah[mi], bh[ni]);
        }

        if (c + 1 < NC) CP_WAIT0();
        __syncthreads();
    }

    // ---- epilogue ----
    const int qrow = lane >> 2;
    const int qcol = (lane & 3) * 2;
    #pragma unroll
    for (int mi = 0; mi < 4; mi++) {
        int gr0 = row0 + wm * 64 + mi * 16 + qrow;
        int gr1 = gr0 + 8;
        int or0 = (EPI == EPI_RES_MAP) ? wr2t(gr0) : gr0;
        int or1 = (EPI == EPI_RES_MAP) ? wr2t(gr1) : gr1;
        #pragma unroll
        for (int ni = 0; ni < 4; ni++) {
            int col = col0 + wn * 32 + ni * 8 + qcol;
            float b0 = bias[col], b1 = bias[col + 1];
            float v00 = acc[mi][ni][0] + b0, v01 = acc[mi][ni][1] + b1;
            float v10 = acc[mi][ni][2] + b0, v11 = acc[mi][ni][3] + b1;
            if (EPI == EPI_GELU) {
                v00 = gelu_exact(v00); v01 = gelu_exact(v01);
                v10 = gelu_exact(v10); v11 = gelu_exact(v11);
            }
            if (EPI == EPI_RES_MAP || EPI == EPI_RES_NAT) {
                float2 r0v = *(const float2*)(R + (size_t)or0 * N + col);
                float2 r1v = *(const float2*)(R + (size_t)or1 * N + col);
                v00 += r0v.x; v01 += r0v.y; v10 += r1v.x; v11 += r1v.y;
            }
            if (OUTH) {
                *(__half2*)(Ch + (size_t)or0 * N + col) =
                    __halves2half2(__float2half_rn(v00), __float2half_rn(v01));
                *(__half2*)(Ch + (size_t)or1 * N + col) =
                    __halves2half2(__float2half_rn(v10), __float2half_rn(v11));
            } else {
                *(float2*)(C + (size_t)or0 * N + col) = make_float2(v00, v01);
                *(float2*)(C + (size_t)or1 * N + col) = make_float2(v10, v11);
            }
        }
    }
}

// ---------------- windowed attention: one block per (window, head) -------
__global__ __launch_bounds__(256)
void attn_kernel(const float* __restrict__ qkv, __half* __restrict__ out)
{
    extern __shared__ float smf[];
    float* qts = smf;
    float* kts = smf + 64 * 65;
    float* vs  = smf + 2 * 64 * 65;
    float* ps  = smf;

    const int tid  = threadIdx.x;
    const int win  = blockIdx.x >> 3;
    const int head = blockIdx.x & 7;
    const size_t base0 = (size_t)win * 64 * QKVN + head * HD;

    for (int e = tid; e < 4096; e += 256) {
        int n = e >> 6, dd = e & 63;
        size_t base = base0 + (size_t)n * QKVN + dd;
        qts[dd * 65 + n] = qkv[base];
        kts[dd * 65 + n] = qkv[base + 512];
        vs[n * 64 + dd]  = qkv[base + 1024];
    }
    __syncthreads();

    const int tx = tid & 15, ty = tid >> 4;
    float acc[4][4] = {};
    #pragma unroll 4
    for (int dd = 0; dd < 64; dd++) {
        float qa[4], kb[4];
        #pragma unroll
        for (int i = 0; i < 4; i++) qa[i] = qts[dd * 65 + ty * 4 + i];
        #pragma unroll
        for (int j = 0; j < 4; j++) kb[j] = kts[dd * 65 + tx * 4 + j];
        #pragma unroll
        for (int i = 0; i < 4; i++)
            #pragma unroll
            for (int j = 0; j < 4; j++)
                acc[i][j] = fmaf(qa[i], kb[j], acc[i][j]);
    }
    __syncthreads();
    #pragma unroll
    for (int i = 0; i < 4; i++)
        #pragma unroll
        for (int j = 0; j < 4; j++)
            ps[(ty * 4 + i) * 64 + tx * 4 + j] = acc[i][j] * 0.125f;
    __syncthreads();

    {
        int w = tid >> 5, lane = tid & 31;
        #pragma unroll
        for (int rr = 0; rr < 8; rr++) {
            int row = w * 8 + rr;
            float a = ps[row * 64 + lane];
            float b = ps[row * 64 + lane + 32];
            float mx = fmaxf(a, b);
            #pragma unroll
            for (int off = 16; off > 0; off >>= 1)
                mx = fmaxf(mx, __shfl_xor_sync(0xffffffffu, mx, off));
            float ea = __expf(a - mx), eb = __expf(b - mx);
            float s = ea + eb;
            #pragma unroll
            for (int off = 16; off > 0; off >>= 1)
                s += __shfl_xor_sync(0xffffffffu, s, off);
            float inv = 1.0f / s;
            ps[row * 64 + lane]      = ea * inv;
            ps[row * 64 + lane + 32] = eb * inv;
        }
    }
    __syncthreads();

    float o[4][4] = {};
    #pragma unroll 4
    for (int m = 0; m < 64; m++) {
        float pv[4], vv[4];
        #pragma unroll
        for (int i = 0; i < 4; i++) pv[i] = ps[(ty * 4 + i) * 64 + m];
        #pragma unroll
        for (int j = 0; j < 4; j++) vv[j] = vs[m * 64 + tx * 4 + j];
        #pragma unroll
        for (int i = 0; i < 4; i++)
            #pragma unroll
            for (int j = 0; j < 4; j++)
                o[i][j] = fmaf(pv[i], vv[j], o[i][j]);
    }
    #pragma unroll
    for (int i = 0; i < 4; i++) {
        int n = ty * 4 + i;
        size_t ob = ((size_t)(win * 64 + n)) * CDIM + head * HD + tx * 4;
        *(__half2*)(out + ob)     = __halves2half2(__float2half_rn(o[i][0]), __float2half_rn(o[i][1]));
        *(__half2*)(out + ob + 2) = __halves2half2(__float2half_rn(o[i][2]), __float2half_rn(o[i][3]));
    }
}

// ---------------- launch ----------------
extern "C" void kernel_launch(void* const* d_in, const int* in_sizes, int n_in,
                              void* d_out, int out_size)
{
    const float* x      = (const float*)d_in[0];
    const float* ln1_g  = (const float*)d_in[1];
    const float* ln1_b  = (const float*)d_in[2];
    const float* qkv_w  = (const float*)d_in[3];
    const float* qkv_b  = (const float*)d_in[4];
    const float* proj_w = (const float*)d_in[5];
    const float* proj_b = (const float*)d_in[6];
    const float* ln2_g  = (const float*)d_in[7];
    const float* ln2_b  = (const float*)d_in[8];
    const float* ffn_w1 = (const float*)d_in[9];
    const float* ffn_b1 = (const float*)d_in[10];
    const float* ffn_w2 = (const float*)d_in[11];
    const float* ffn_b2 = (const float*)d_in[12];
    float* out = (float*)d_out;

    void* p;
    cudaGetSymbolAddress(&p, g_qkv);  float* qkvb = (float*)p;
    cudaGetSymbolAddress(&p, g_xo);   float* xo   = (float*)p;
    __half *y1, *at, *y2, *hid;
    cudaGetSymbolAddress(&p, g_y1);  y1  = (__half*)p;
    cudaGetSymbolAddress(&p, g_at);  at  = (__half*)p;
    cudaGetSymbolAddress(&p, g_y2);  y2  = (__half*)p;
    cudaGetSymbolAddress(&p, g_hid); hid = (__half*)p;
    __half *wqh, *wql, *wph, *wpl, *w1h, *w1l, *w2h, *w2l;
    cudaGetSymbolAddress(&p, g_wqkv_hi); wqh = (__half*)p;
    cudaGetSymbolAddress(&p, g_wqkv_lo); wql = (__half*)p;
    cudaGetSymbolAddress(&p, g_wprj_hi); wph = (__half*)p;
    cudaGetSymbolAddress(&p, g_wprj_lo); wpl = (__half*)p;
    cudaGetSymbolAddress(&p, g_w1_hi);   w1h = (__half*)p;
    cudaGetSymbolAddress(&p, g_w1_lo);   w1l = (__half*)p;
    cudaGetSymbolAddress(&p, g_w2_hi);   w2h = (__half*)p;
    cudaGetSymbolAddress(&p, g_w2_lo);   w2l = (__half*)p;

    const int smem_attn = (2 * 64 * 65 + 64 * 64) * 4;
    cudaFuncSetAttribute(attn_kernel, cudaFuncAttributeMaxDynamicSharedMemorySize, smem_attn);
    cudaFuncSetAttribute(gemm_mma<EPI_NONE, 0>,    cudaFuncAttributeMaxDynamicSharedMemorySize, GT_SMEM);
    cudaFuncSetAttribute(gemm_mma<EPI_GELU, 1>,    cudaFuncAttributeMaxDynamicSharedMemorySize, GT_SMEM);
    cudaFuncSetAttribute(gemm_mma<EPI_RES_MAP, 0>, cudaFuncAttributeMaxDynamicSharedMemorySize, GT_SMEM);
    cudaFuncSetAttribute(gemm_mma<EPI_RES_NAT, 0>, cudaFuncAttributeMaxDynamicSharedMemorySize, GT_SMEM);

    // 0) weight transpose + fp16 split
    wsplit_kernel<<<dim3(QKVN / 32, CDIM / 32), 256>>>(qkv_w,  CDIM, QKVN, wqh, wql);
    wsplit_kernel<<<dim3(CDIM / 32, CDIM / 32), 256>>>(proj_w, CDIM, CDIM, wph, wpl);
    wsplit_kernel<<<dim3(HIDN / 32, CDIM / 32), 256>>>(ffn_w1, CDIM, HIDN, w1h, w1l);
    wsplit_kernel<<<dim3(CDIM / 32, HIDN / 32), 256>>>(ffn_w2, HIDN, CDIM, w2h, w2l);

    // 1) LN1 with shift+window gather -> fp16
    ln_kernel<<<TOK, 256>>>(x, ln1_g, ln1_b, y1, 1);

    // 2) QKV GEMM -> fp32 qkv
    gemm_mma<EPI_NONE, 0><<<dim3(QKVN / 128, TOK / 128), 256, GT_SMEM>>>(
        y1, wqh, wql, qkv_b, nullptr, qkvb, nullptr, TOK, QKVN, CDIM);

    // 3) attention -> fp16
    attn_kernel<<<NWIN * NHEAD, 256, smem_attn>>>(qkvb, at);

    // 4) proj GEMM + residual(x) + scatter -> fp32 xo (natural)
    gemm_mma<EPI_RES_MAP, 0><<<dim3(CDIM / 128, TOK / 128), 256, GT_SMEM>>>(
        at, wph, wpl, proj_b, x, xo, nullptr, TOK, CDIM, CDIM);

    // 5) LN2 -> fp16
    ln_kernel<<<TOK, 256>>>(xo, ln2_g, ln2_b, y2, 0);

    // 6) FFN1 + GELU -> fp16 hidden
    gemm_mma<EPI_GELU, 1><<<dim3(HIDN / 128, TOK / 128), 256, GT_SMEM>>>(
        y2, w1h, w1l, ffn_b1, nullptr, nullptr, hid, TOK, HIDN, CDIM);

    // 7) FFN2 + residual(xo) -> out
    gemm_mma<EPI_RES_NAT, 0><<<dim3(CDIM / 128, TOK / 128), 256, GT_SMEM>>>(
        hid, w2h, w2l, ffn_b2, xo, out, nullptr, TOK, CDIM, HIDN);
}

// round 7
// speedup vs baseline: 4.8001x; 1.4126x over previous
#include <cuda_runtime.h>
#include <cuda_fp16.h>
#include <cstdint>
#include <math.h>

// ---------------- problem constants ----------------
#define TOK   65536          // 2*32*32*32 tokens
#define CDIM  512
#define QKVN  1536
#define HIDN  2048
#define NWIN  1024           // windows total (2 * 8^3)
#define NHEAD 8
#define HD    64

// ---------------- helpers ----------------
__device__ __forceinline__ uint32_t smem_to_u32(const void* p) {
    uint32_t a;
    asm("{ .reg .u64 t; cvta.to.shared.u64 t, %1; cvt.u32.u64 %0, t; }" : "=r"(a) : "l"(p));
    return a;
}

#define CP_ASYNC16(dst, src) \
    asm volatile("cp.async.cg.shared.global [%0], [%1], 16;" :: "r"(dst), "l"(src))
#define CP_COMMIT() asm volatile("cp.async.commit_group;" ::: "memory")
#define CP_WAIT0()  asm volatile("cp.async.wait_group 0;" ::: "memory")

#define LDSM_X4(r0, r1, r2, r3, addr) \
    asm volatile("ldmatrix.sync.aligned.m8n8.x4.shared.b16 {%0,%1,%2,%3}, [%4];" \
                 : "=r"(r0), "=r"(r1), "=r"(r2), "=r"(r3) : "r"(addr))

__device__ __forceinline__ void mma_f16(float* c, const uint32_t* a, const uint32_t* b) {
    asm volatile(
        "mma.sync.aligned.m16n8k16.row.col.f32.f16.f16.f32 "
        "{%0,%1,%2,%3}, {%4,%5,%6,%7}, {%8,%9}, {%0,%1,%2,%3};"
        : "+f"(c[0]), "+f"(c[1]), "+f"(c[2]), "+f"(c[3])
        : "r"(a[0]), "r"(a[1]), "r"(a[2]), "r"(a[3]), "r"(b[0]), "r"(b[1]));
}

// ---------------- scratch (static device memory) ----------------
__device__ float  g_xo  [(size_t)TOK * CDIM];                 // fp32 residual base
__device__ __half g_qkv [(size_t)TOK * QKVN];                 // fp16 qkv
// fp16 activations (GEMM A-operands)
__device__ __half g_y1 [(size_t)TOK * CDIM];
__device__ __half g_at [(size_t)TOK * CDIM];
__device__ __half g_y2 [(size_t)TOK * CDIM];
__device__ __half g_hid[(size_t)TOK * HIDN];
// weight transposed fp16 buffers: [N, K]
__device__ __half g_wqkv[(size_t)QKVN * CDIM];
__device__ __half g_wprj[(size_t)CDIM * CDIM];
__device__ __half g_w1  [(size_t)HIDN * CDIM];
__device__ __half g_w2  [(size_t)CDIM * HIDN];

// window-ordered row r -> natural token index t
__device__ __forceinline__ int wr2t(int r) {
    int n   = r & 63;
    int win = r >> 6;
    int ww  = win & 7, wh = (win >> 3) & 7, wd = (win >> 6) & 7, b = win >> 9;
    int zw  = n & 3,  zh = (n >> 2) & 3,  zd = n >> 4;
    int d = (wd * 4 + zd + 2) & 31;
    int h = (wh * 4 + zh + 2) & 31;
    int w = (ww * 4 + zw + 2) & 31;
    return ((b * 32 + d) * 32 + h) * 32 + w;
}

__device__ __forceinline__ float gelu_exact(float v) {
    return 0.5f * v * (1.0f + erff(v * 0.70710678118654752f));
}

// ---------------- weight transpose -> fp16 ----------------
__global__ __launch_bounds__(256)
void wconv_kernel(const float* __restrict__ W, int K, int N, __half* __restrict__ Wt)
{
    __shared__ float tile[32][33];
    int n0 = blockIdx.x * 32, k0 = blockIdx.y * 32;
    int tx = threadIdx.x & 31, ty = threadIdx.x >> 5;   // 32 x 8
    #pragma unroll
    for (int r = 0; r < 4; r++) {
        int kk = ty + r * 8;
        tile[kk][tx] = W[(size_t)(k0 + kk) * N + n0 + tx];
    }
    __syncthreads();
    #pragma unroll
    for (int r = 0; r < 4; r++) {
        int nn = ty + r * 8;
        Wt[(size_t)(n0 + nn) * K + k0 + tx] = __float2half_rn(tile[tx][nn]);
    }
}

// ---------------- LayerNorm -> fp16 ----------------
__global__ __launch_bounds__(256)
void ln_kernel(const float* __restrict__ X, const float* __restrict__ gam,
               const float* __restrict__ bet, __half* __restrict__ Y, int gather)
{
    __shared__ float red[16];
    int r   = blockIdx.x;
    int src = gather ? wr2t(r) : r;
    const float* xr = X + (size_t)src * CDIM;
    int t = threadIdx.x;
    float v0 = xr[t], v1 = xr[t + 256];
    float s = v0 + v1;
    float q = v0 * v0 + v1 * v1;
    #pragma unroll
    for (int off = 16; off > 0; off >>= 1) {
        s += __shfl_xor_sync(0xffffffffu, s, off);
        q += __shfl_xor_sync(0xffffffffu, q, off);
    }
    int w = t >> 5, lane = t & 31;
    if (lane == 0) { red[w] = s; red[8 + w] = q; }
    __syncthreads();
    if (w == 0) {
        float s2 = (lane < 8) ? red[lane] : 0.f;
        float q2 = (lane < 8) ? red[8 + lane] : 0.f;
        #pragma unroll
        for (int off = 4; off > 0; off >>= 1) {
            s2 += __shfl_xor_sync(0xffffffffu, s2, off);
            q2 += __shfl_xor_sync(0xffffffffu, q2, off);
        }
        if (lane == 0) { red[0] = s2; red[1] = q2; }
    }
    __syncthreads();
    float mean = red[0] * (1.0f / CDIM);
    float var  = red[1] * (1.0f / CDIM) - mean * mean;
    float rstd = rsqrtf(var + 1e-5f);
    size_t rb = (size_t)r * CDIM;
    float y0 = (v0 - mean) * rstd * gam[t]       + bet[t];
    float y1 = (v1 - mean) * rstd * gam[t + 256] + bet[t + 256];
    Y[rb + t]       = __float2half_rn(y0);
    Y[rb + t + 256] = __float2half_rn(y1);
}

// ---------------- tensor-core GEMM via mma.sync (pure fp16, fp32 acc) ------
// C[M,N] = A[M,K] @ B[K,N] + bias;  A fp16 [M,K], B fp16 [N,K] (pre-transposed).
// CTA 128x128, 8 warps in 2(M)x4(N), warp tile 64x32, BK=32, double buffer.
#define EPI_NONE    0
#define EPI_GELU    1
#define EPI_RES_MAP 2
#define EPI_RES_NAT 3

#define ROWPITCH 80
#define REG_A    0
#define REG_B    10240
#define BUFSZ    20480
#define GT_SMEM  (2 * BUFSZ)

template<int EPI, int OUTH>
__global__ __launch_bounds__(256, 2)
void gemm_mma(const __half* __restrict__ A, const __half* __restrict__ B,
              const float* __restrict__ bias, const float* __restrict__ R,
              float* __restrict__ C, __half* __restrict__ Ch, int M, int N, int K)
{
    extern __shared__ char sm[];
    const uint32_t smb = smem_to_u32(sm);
    const int tid  = threadIdx.x;
    const int wid  = tid >> 5, lane = tid & 31;
    const int wm   = wid & 1,  wn   = wid >> 1;
    const int row0 = blockIdx.y * 128, col0 = blockIdx.x * 128;

    const int s0row = tid >> 2, s0k8 = (tid & 3) * 8;   // seg tid
    const int s1row = s0row + 64;                        // seg tid + 256
    const uint32_t so0 = (uint32_t)(s0row * ROWPITCH + s0k8 * 2);
    const uint32_t so1 = (uint32_t)(s1row * ROWPITCH + s0k8 * 2);

    const int g = lane >> 3, r = lane & 7;
    const uint32_t aoff = (uint32_t)((wm * 64 + (g & 1) * 8 + r) * ROWPITCH + (g >> 1) * 16);
    const uint32_t boff = (uint32_t)(((g >> 1) * 8 + r + wn * 32) * ROWPITCH + (g & 1) * 16);

    float acc[4][4][4];
    #pragma unroll
    for (int i = 0; i < 4; i++)
        #pragma unroll
        for (int j = 0; j < 4; j++)
            #pragma unroll
            for (int e = 0; e < 4; e++) acc[i][j][e] = 0.f;

    const int NC = K >> 5;

    auto load_chunk = [&](int kc, int buf) {
        const uint32_t bb = smb + buf * BUFSZ;
        size_t ga0 = (size_t)(row0 + s0row) * K + kc + s0k8;
        size_t ga1 = (size_t)(row0 + s1row) * K + kc + s0k8;
        CP_ASYNC16(bb + REG_A + so0, A + ga0);
        CP_ASYNC16(bb + REG_A + so1, A + ga1);
        size_t gb0 = (size_t)(col0 + s0row) * K + kc + s0k8;
        size_t gb1 = (size_t)(col0 + s1row) * K + kc + s0k8;
        CP_ASYNC16(bb + REG_B + so0, B + gb0);
        CP_ASYNC16(bb + REG_B + so1, B + gb1);
        CP_COMMIT();
    };

    load_chunk(0, 0);
    CP_WAIT0();
    __syncthreads();

    for (int c = 0; c < NC; c++) {
        const int buf = c & 1;
        const uint32_t ab = smb + buf * BUFSZ;

        if (c + 1 < NC) load_chunk((c + 1) * 32, buf ^ 1);

        #pragma unroll
        for (int s = 0; s < 2; s++) {
            uint32_t ah[4][4], bh[4][2];
            #pragma unroll
            for (int mi = 0; mi < 4; mi++) {
                uint32_t addr = ab + aoff + mi * (16 * ROWPITCH) + s * 32;
                LDSM_X4(ah[mi][0], ah[mi][1], ah[mi][2], ah[mi][3], addr + REG_A);
            }
            #pragma unroll
            for (int nj = 0; nj < 2; nj++) {
                uint32_t addr = ab + boff + nj * (16 * ROWPITCH) + s * 32;
                LDSM_X4(bh[nj*2][0], bh[nj*2][1], bh[nj*2+1][0], bh[nj*2+1][1], addr + REG_B);
            }
            #pragma unroll
            for (int mi = 0; mi < 4; mi++)
                #pragma unroll
                for (int ni = 0; ni < 4; ni++)
                    mma_f16(acc[mi][ni], ah[mi], bh[ni]);
        }

        if (c + 1 < NC) CP_WAIT0();
        __syncthreads();
    }

    // ---- epilogue ----
    const int qrow = lane >> 2;
    const int qcol = (lane & 3) * 2;
    #pragma unroll
    for (int mi = 0; mi < 4; mi++) {
        int gr0 = row0 + wm * 64 + mi * 16 + qrow;
        int gr1 = gr0 + 8;
        int or0 = (EPI == EPI_RES_MAP) ? wr2t(gr0) : gr0;
        int or1 = (EPI == EPI_RES_MAP) ? wr2t(gr1) : gr1;
        #pragma unroll
        for (int ni = 0; ni < 4; ni++) {
            int col = col0 + wn * 32 + ni * 8 + qcol;
            float b0 = bias[col], b1 = bias[col + 1];
            float v00 = acc[mi][ni][0] + b0, v01 = acc[mi][ni][1] + b1;
            float v10 = acc[mi][ni][2] + b0, v11 = acc[mi][ni][3] + b1;
            if (EPI == EPI_GELU) {
                v00 = gelu_exact(v00); v01 = gelu_exact(v01);
                v10 = gelu_exact(v10); v11 = gelu_exact(v11);
            }
            if (EPI == EPI_RES_MAP || EPI == EPI_RES_NAT) {
                float2 r0v = *(const float2*)(R + (size_t)or0 * N + col);
                float2 r1v = *(const float2*)(R + (size_t)or1 * N + col);
                v00 += r0v.x; v01 += r0v.y; v10 += r1v.x; v11 += r1v.y;
            }
            if (OUTH) {
                *(__half2*)(Ch + (size_t)or0 * N + col) =
                    __halves2half2(__float2half_rn(v00), __float2half_rn(v01));
                *(__half2*)(Ch + (size_t)or1 * N + col) =
                    __halves2half2(__float2half_rn(v10), __float2half_rn(v11));
            } else {
                *(float2*)(C + (size_t)or0 * N + col) = make_float2(v00, v01);
                *(float2*)(C + (size_t)or1 * N + col) = make_float2(v10, v11);
            }
        }
    }
}

// ---------------- windowed attention: one block per (window, head) -------
__global__ __launch_bounds__(256)
void attn_kernel(const __half* __restrict__ qkv, __half* __restrict__ out)
{
    extern __shared__ float smf[];
    float* qts = smf;
    float* kts = smf + 64 * 65;
    float* vs  = smf + 2 * 64 * 65;
    float* ps  = smf;

    const int tid  = threadIdx.x;
    const int win  = blockIdx.x >> 3;
    const int head = blockIdx.x & 7;
    const size_t base0 = (size_t)win * 64 * QKVN + head * HD;

    for (int e = tid; e < 4096; e += 256) {
        int n = e >> 6, dd = e & 63;
        size_t base = base0 + (size_t)n * QKVN + dd;
        qts[dd * 65 + n] = __half2float(qkv[base]);
        kts[dd * 65 + n] = __half2float(qkv[base + 512]);
        vs[n * 64 + dd]  = __half2float(qkv[base + 1024]);
    }
    __syncthreads();

    const int tx = tid & 15, ty = tid >> 4;
    float acc[4][4] = {};
    #pragma unroll 4
    for (int dd = 0; dd < 64; dd++) {
        float qa[4], kb[4];
        #pragma unroll
        for (int i = 0; i < 4; i++) qa[i] = qts[dd * 65 + ty * 4 + i];
        #pragma unroll
        for (int j = 0; j < 4; j++) kb[j] = kts[dd * 65 + tx * 4 + j];
        #pragma unroll
        for (int i = 0; i < 4; i++)
            #pragma unroll
            for (int j = 0; j < 4; j++)
                acc[i][j] = fmaf(qa[i], kb[j], acc[i][j]);
    }
    __syncthreads();
    #pragma unroll
    for (int i = 0; i < 4; i++)
        #pragma unroll
        for (int j = 0; j < 4; j++)
            ps[(ty * 4 + i) * 64 + tx * 4 + j] = acc[i][j] * 0.125f;
    __syncthreads();

    {
        int w = tid >> 5, lane = tid & 31;
        #pragma unroll
        for (int rr = 0; rr < 8; rr++) {
            int row = w * 8 + rr;
            float a = ps[row * 64 + lane];
            float b = ps[row * 64 + lane + 32];
            float mx = fmaxf(a, b);
            #pragma unroll
            for (int off = 16; off > 0; off >>= 1)
                mx = fmaxf(mx, __shfl_xor_sync(0xffffffffu, mx, off));
            float ea = __expf(a - mx), eb = __expf(b - mx);
            float s = ea + eb;
            #pragma unroll
            for (int off = 16; off > 0; off >>= 1)
                s += __shfl_xor_sync(0xffffffffu, s, off);
            float inv = 1.0f / s;
            ps[row * 64 + lane]      = ea * inv;
            ps[row * 64 + lane + 32] = eb * inv;
        }
    }
    __syncthreads();

    float o[4][4] = {};
    #pragma unroll 4
    for (int m = 0; m < 64; m++) {
        float pv[4], vv[4];
        #pragma unroll
        for (int i = 0; i < 4; i++) pv[i] = ps[(ty * 4 + i) * 64 + m];
        #pragma unroll
        for (int j = 0; j < 4; j++) vv[j] = vs[m * 64 + tx * 4 + j];
        #pragma unroll
        for (int i = 0; i < 4; i++)
            #pragma unroll
            for (int j = 0; j < 4; j++)
                o[i][j] = fmaf(pv[i], vv[j], o[i][j]);
    }
    #pragma unroll
    for (int i = 0; i < 4; i++) {
        int n = ty * 4 + i;
        size_t ob = ((size_t)(win * 64 + n)) * CDIM + head * HD + tx * 4;
        *(__half2*)(out + ob)     = __halves2half2(__float2half_rn(o[i][0]), __float2half_rn(o[i][1]));
        *(__half2*)(out + ob + 2) = __halves2half2(__float2half_rn(o[i][2]), __float2half_rn(o[i][3]));
    }
}

// ---------------- launch ----------------
extern "C" void kernel_launch(void* const* d_in, const int* in_sizes, int n_in,
                              void* d_out, int out_size)
{
    const float* x      = (const float*)d_in[0];
    const float* ln1_g  = (const float*)d_in[1];
    const float* ln1_b  = (const float*)d_in[2];
    const float* qkv_w  = (const float*)d_in[3];
    const float* qkv_b  = (const float*)d_in[4];
    const float* proj_w = (const float*)d_in[5];
    const float* proj_b = (const float*)d_in[6];
    const float* ln2_g  = (const float*)d_in[7];
    const float* ln2_b  = (const float*)d_in[8];
    const float* ffn_w1 = (const float*)d_in[9];
    const float* ffn_b1 = (const float*)d_in[10];
    const float* ffn_w2 = (const float*)d_in[11];
    const float* ffn_b2 = (const float*)d_in[12];
    float* out = (float*)d_out;

    void* p;
    cudaGetSymbolAddress(&p, g_xo);   float* xo = (float*)p;
    __half *qkvb, *y1, *at, *y2, *hid;
    cudaGetSymbolAddress(&p, g_qkv); qkvb = (__half*)p;
    cudaGetSymbolAddress(&p, g_y1);  y1   = (__half*)p;
    cudaGetSymbolAddress(&p, g_at);  at   = (__half*)p;
    cudaGetSymbolAddress(&p, g_y2);  y2   = (__half*)p;
    cudaGetSymbolAddress(&p, g_hid); hid  = (__half*)p;
    __half *wq, *wp, *w1, *w2;
    cudaGetSymbolAddress(&p, g_wqkv); wq = (__half*)p;
    cudaGetSymbolAddress(&p, g_wprj); wp = (__half*)p;
    cudaGetSymbolAddress(&p, g_w1);   w1 = (__half*)p;
    cudaGetSymbolAddress(&p, g_w2);   w2 = (__half*)p;

    const int smem_attn = (2 * 64 * 65 + 64 * 64) * 4;
    cudaFuncSetAttribute(attn_kernel, cudaFuncAttributeMaxDynamicSharedMemorySize, smem_attn);
    cudaFuncSetAttribute(gemm_mma<EPI_NONE, 1>,    cudaFuncAttributeMaxDynamicSharedMemorySize, GT_SMEM);
    cudaFuncSetAttribute(gemm_mma<EPI_GELU, 1>,    cudaFuncAttributeMaxDynamicSharedMemorySize, GT_SMEM);
    cudaFuncSetAttribute(gemm_mma<EPI_RES_MAP, 0>, cudaFuncAttributeMaxDynamicSharedMemorySize, GT_SMEM);
    cudaFuncSetAttribute(gemm_mma<EPI_RES_NAT, 0>, cudaFuncAttributeMaxDynamicSharedMemorySize, GT_SMEM);

    // 0) weight transpose -> fp16
    wconv_kernel<<<dim3(QKVN / 32, CDIM / 32), 256>>>(qkv_w,  CDIM, QKVN, wq);
    wconv_kernel<<<dim3(CDIM / 32, CDIM / 32), 256>>>(proj_w, CDIM, CDIM, wp);
    wconv_kernel<<<dim3(HIDN / 32, CDIM / 32), 256>>>(ffn_w1, CDIM, HIDN, w1);
    wconv_kernel<<<dim3(CDIM / 32, HIDN / 32), 256>>>(ffn_w2, HIDN, CDIM, w2);

    // 1) LN1 with shift+window gather -> fp16
    ln_kernel<<<TOK, 256>>>(x, ln1_g, ln1_b, y1, 1);

    // 2) QKV GEMM -> fp16 qkv
    gemm_mma<EPI_NONE, 1><<<dim3(QKVN / 128, TOK / 128), 256, GT_SMEM>>>(
        y1, wq, qkv_b, nullptr, nullptr, qkvb, TOK, QKVN, CDIM);

    // 3) attention -> fp16
    attn_kernel<<<NWIN * NHEAD, 256, smem_attn>>>(qkvb, at);

    // 4) proj GEMM + residual(x) + scatter -> fp32 xo (natural)
    gemm_mma<EPI_RES_MAP, 0><<<dim3(CDIM / 128, TOK / 128), 256, GT_SMEM>>>(
        at, wp, proj_b, x, xo, nullptr, TOK, CDIM, CDIM);

    // 5) LN2 -> fp16
    ln_kernel<<<TOK, 256>>>(xo, ln2_g, ln2_b, y2, 0);

    // 6) FFN1 + GELU -> fp16 hidden
    gemm_mma<EPI_GELU, 1><<<dim3(HIDN / 128, TOK / 128), 256, GT_SMEM>>>(
        y2, w1, ffn_b1, nullptr, nullptr, hid, TOK, HIDN, CDIM);

    // 7) FFN2 + residual(xo) -> out
    gemm_mma<EPI_RES_NAT, 0><<<dim3(CDIM / 128, TOK / 128), 256, GT_SMEM>>>(
        hid, w2, ffn_b2, xo, out, nullptr, TOK, CDIM, HIDN);
}